// round 11
// baseline (speedup 1.0000x reference)
#include <cuda_runtime.h>
#include <cuda_fp16.h>
#include <math.h>
#include <stdint.h>

#define MTOT 16384

// ---------------- scratch ----------------
__device__ __align__(1024) __half g_xall[(size_t)MTOT * 512];
__device__ __align__(1024) __half g_q   [(size_t)MTOT * 256];
__device__ __align__(1024) __half g_kv  [(size_t)MTOT * 512];
__device__ __align__(1024) __half g_h1  [(size_t)MTOT * 256];
__device__ float  g_offs[(size_t)MTOT * 18];
__device__ __align__(1024) __half g_att [(size_t)MTOT * 256];
__device__ float  g_xres[(size_t)MTOT * 256];
__device__ __align__(1024) __half g_xn2 [(size_t)MTOT * 256];
__device__ __align__(1024) __half g_hid [(size_t)MTOT * 1024];
__device__ __align__(1024) __half g_wr  [256 * 4608];
__device__ __align__(1024) __half g_wh  [65536 + 131072 + 65536 + 262144 + 262144];
__device__ float2 g_part[256];
__device__ float  g_st1 [16];
__device__ float  g_st2 [8];

// ---------------- fused weight prep: conv repack + 5x f2h ----------------
__global__ void prep_k(const float* __restrict__ off1_w, __half* __restrict__ wr,
                       const float* __restrict__ q_w,    __half* __restrict__ qwh,
                       const float* __restrict__ kv_w,   __half* __restrict__ kvwh,
                       const float* __restrict__ proj_w, __half* __restrict__ pwh,
                       const float* __restrict__ fc1_w,  __half* __restrict__ f1wh,
                       const float* __restrict__ fc2_w,  __half* __restrict__ f2wh) {
    int id = blockIdx.x * 256 + threadIdx.x;
    if (id < 1179648) {
        int o = id / 4608, k = id - o * 4608;
        int nb = k >> 9, c = k & 511;
        int ky = nb / 3, kx = nb - ky * 3;
        wr[id] = __float2half(off1_w[((size_t)o * 512 + c) * 9 + ky * 3 + kx]);
        return;
    }
    id -= 1179648;
    if (id < 65536)  { qwh [id] = __float2half(q_w [id]); return; }  id -= 65536;
    if (id < 131072) { kvwh[id] = __float2half(kv_w[id]); return; }  id -= 131072;
    if (id < 65536)  { pwh [id] = __float2half(proj_w[id]); return; } id -= 65536;
    if (id < 262144) { f1wh[id] = __float2half(fc1_w[id]); return; }  id -= 262144;
    f2wh[id] = __float2half(fc2_w[id]);
}

// ---------------- groupnorm stats: phase 1 ----------------
__global__ void gn_p1(const float* __restrict__ A, const float* __restrict__ B2,
                      float2* __restrict__ part) {
    int bi = blockIdx.x;
    int slab = bi >> 5, chunk = bi & 31;
    int tensor = slab >> 2, batch = slab & 3;
    const float* src = (tensor ? B2 : A) + ((size_t)batch << 20) + ((size_t)chunk << 15);
    const float4* p4 = reinterpret_cast<const float4*>(src);
    float s = 0.f, s2 = 0.f;
    for (int i = threadIdx.x; i < 8192; i += 256) {
        float4 v = p4[i];
        s  += v.x + v.y + v.z + v.w;
        s2 += v.x * v.x + v.y * v.y + v.z * v.z + v.w * v.w;
    }
    __shared__ float sh1[256], sh2[256];
    sh1[threadIdx.x] = s; sh2[threadIdx.x] = s2;
    __syncthreads();
    for (int st = 128; st > 0; st >>= 1) {
        if (threadIdx.x < st) { sh1[threadIdx.x] += sh1[threadIdx.x + st];
                                sh2[threadIdx.x] += sh2[threadIdx.x + st]; }
        __syncthreads();
    }
    if (threadIdx.x == 0) part[slab * 32 + chunk] = make_float2(sh1[0], sh2[0]);
}

// ---------------- groupnorm stats: phase 2 ----------------
__global__ void gn_p2(const float2* __restrict__ part, float* __restrict__ stats, int nslab) {
    int slab = threadIdx.x >> 5, lane = threadIdx.x & 31;
    if (slab >= nslab) return;
    float2 v = part[slab * 32 + lane];
    float s = v.x, s2 = v.y;
#pragma unroll
    for (int off = 16; off > 0; off >>= 1) {
        s  += __shfl_xor_sync(0xffffffffu, s,  off);
        s2 += __shfl_xor_sync(0xffffffffu, s2, off);
    }
    if (lane == 0) {
        float inv = 1.f / 1048576.f;
        float mu = s * inv;
        float var = s2 * inv - mu * mu;
        stats[slab * 2] = mu;
        stats[slab * 2 + 1] = rsqrtf(var + 1e-5f);
    }
}

// ---------------- normalize + NCHW->NHWC pack (fp16 out) ----------------
__global__ void norm_pack_k(const float* __restrict__ xq, const float* __restrict__ xkv,
                            const float* __restrict__ stats, const float* __restrict__ w,
                            const float* __restrict__ bb, __half* __restrict__ xall) {
    __shared__ float tile[32][33];
    int bz = blockIdx.z;
    int tensor = bz >> 2, batch = bz & 3;
    const float* src = (tensor == 0 ? xq : xkv) + ((size_t)batch << 20);
    float mu = stats[bz * 2], rstd = stats[bz * 2 + 1];
    int s0 = blockIdx.x * 32, c0 = blockIdx.y * 32;
    int tx = threadIdx.x, ty = threadIdx.y;
#pragma unroll
    for (int k = 0; k < 4; k++) {
        int c = c0 + ty + k * 8;
        tile[ty + k * 8][tx] = src[(size_t)c * 4096 + s0 + tx];
    }
    __syncthreads();
#pragma unroll
    for (int k = 0; k < 4; k++) {
        int sl = ty + k * 8;
        int c = c0 + tx;
        float v = (tile[tx][sl] - mu) * rstd * w[c] + bb[c];
        xall[(((size_t)batch * 4096 + s0 + sl) << 9) + tensor * 256 + c] = __float2half(v);
    }
}

// ---------------- norm2 (fp16 out) ----------------
__global__ void norm2_k(const float* __restrict__ xres, const float* __restrict__ stats,
                        const float* __restrict__ w, const float* __restrict__ bb,
                        __half* __restrict__ xn) {
    int id = blockIdx.x * blockDim.x + threadIdx.x;
    if (id >= MTOT * 256) return;
    int b = id >> 20, c = id & 255;
    xn[id] = __float2half((xres[id] - stats[b * 2]) * stats[b * 2 + 1] * w[c] + bb[c]);
}

// ---------------- PTX helpers ----------------
__device__ __forceinline__ void mma16(float4& d, const uint32_t* a, const uint32_t* b) {
    asm volatile("mma.sync.aligned.m16n8k16.row.col.f32.f16.f16.f32 "
        "{%0,%1,%2,%3}, {%4,%5,%6,%7}, {%8,%9}, {%0,%1,%2,%3};\n"
        : "+f"(d.x), "+f"(d.y), "+f"(d.z), "+f"(d.w)
        : "r"(a[0]), "r"(a[1]), "r"(a[2]), "r"(a[3]), "r"(b[0]), "r"(b[1]));
}
__device__ __forceinline__ void ldsm4(uint32_t* r, uint32_t a) {
    asm volatile("ldmatrix.sync.aligned.m8n8.x4.shared.b16 {%0,%1,%2,%3}, [%4];"
        : "=r"(r[0]), "=r"(r[1]), "=r"(r[2]), "=r"(r[3]) : "r"(a));
}
__device__ __forceinline__ void cp16(uint32_t d, const void* s, int sz) {
    asm volatile("cp.async.cg.shared.global [%0], [%1], 16, %2;"
        :: "r"(d), "l"(s), "r"(sz));
}
#define CP_COMMIT() asm volatile("cp.async.commit_group;")

// ---------------- multi-job fp16 tensor-core GEMM ----------------
// C[M,N] = A[M,K] @ W[N,K]^T + bias (A, W fp16; accum/bias fp32). M = 16384.
// half-out modes: 1 *scale  2 relu  3 gelu  6 plain
// fp32 modes:     4 +R(NCHW)->NHWC  5 +R(NHWC)->NCHW
// CTA tile 128x128x64(halves), 256 thr, 3-stage cp.async, mma m16n8k16, 2 CTA/SM.
#define STG_BYTES 32768
#define SMEM_REQ  (3 * STG_BYTES)

struct GJob {
    const __half* A; const __half* W; const float* bias; float* C; const float* R;
    int N, K, lda, mode, im2col; float scale;
};

__device__ __forceinline__ void issue_tile(
    uint32_t sa0, const __half* __restrict__ A, const __half* __restrict__ W,
    int bm, int bn, int K0, int lda, int K, int im2col, int lrow, int g)
{
    uint32_t sa = sa0 + lrow * 128;
    const __half* srcA; int szA = 16;
    if (!im2col) {
        srcA = A + (size_t)(bm + lrow) * lda + K0;
    } else {
        const int gm = bm + lrow;
        const int ib = gm >> 12, sp = gm & 4095;
        const int iy = sp >> 6, ix = sp & 63;
        const int nb = K0 >> 9, cc0 = K0 & 511;
        const int qy = nb / 3;
        const int yy = iy + qy - 1, xx = ix + (nb - qy * 3) - 1;
        srcA = A + (((size_t)(ib << 12) + (yy << 6) + xx) << 9) + cc0;
        if (!(yy >= 0 && yy < 64 && xx >= 0 && xx < 64)) { szA = 0; srcA = A; }
    }
    const __half* srcB = W + (size_t)(bn + lrow) * (size_t)K + K0;
    const int r7 = lrow & 7;
#pragma unroll
    for (int j = 0; j < 4; j++) {
        const int c = g + j;
        const uint32_t off = (uint32_t)((c ^ r7) << 4);
        cp16(sa + off, srcA + c * 8, szA);
        cp16(sa + 16384 + off, srcB + c * 8, 16);
    }
}

__global__ void __launch_bounds__(256, 2) gemm_tc(
    GJob j0, GJob j1, GJob j2, int c0, int c1)
{
    extern __shared__ float smbuf[];
    const uint32_t smem_base = (uint32_t)__cvta_generic_to_shared(smbuf);

    GJob J;
    int local;
    {
        const int id = blockIdx.x;
        if (id < c0)      { J = j0; local = id; }
        else if (id < c1) { J = j1; local = id - c0; }
        else              { J = j2; local = id - c1; }
    }
    const int bnb = J.N >> 7;
    const int bm = (local / bnb) << 7, bn = (local % bnb) << 7;

    const int tid  = threadIdx.x;
    const int warp = tid >> 5, lane = tid & 31;
    const int wm   = (warp >> 2) << 6, wn = (warp & 3) << 5;
    const int lg   = lane >> 2, la3 = lane & 3;

    const int lrow = tid >> 1, g = (tid & 1) * 4;

    const int l7 = lane & 7, lq = lane >> 3;
    uint32_t arow[4], brow[2];
#pragma unroll
    for (int mt = 0; mt < 4; mt++)
        arow[mt] = (uint32_t)((wm + mt * 16 + ((lq & 1) << 3) + l7) * 128);
    const int a_kq = lq >> 1;
#pragma unroll
    for (int p = 0; p < 2; p++)
        brow[p] = (uint32_t)(16384 + (wn + p * 16 + ((lq >> 1) << 3) + l7) * 128);
    const int b_kq = lq & 1;

    float4 acc[4][4];
#pragma unroll
    for (int i = 0; i < 4; i++)
#pragma unroll
        for (int j = 0; j < 4; j++) acc[i][j] = make_float4(0.f, 0.f, 0.f, 0.f);

    const int nkb = J.K >> 6;
    issue_tile(smem_base,             J.A, J.W, bm, bn,  0, J.lda, J.K, J.im2col, lrow, g);
    CP_COMMIT();
    issue_tile(smem_base + STG_BYTES, J.A, J.W, bm, bn, 64, J.lda, J.K, J.im2col, lrow, g);
    CP_COMMIT();

    int stg = 0;
    for (int kb = 0; kb < nkb; kb++) {
        asm volatile("cp.async.wait_group 1;");
        __syncthreads();
        if (kb + 2 < nkb) {
            int s2 = stg + 2; if (s2 >= 3) s2 -= 3;
            issue_tile(smem_base + s2 * STG_BYTES, J.A, J.W, bm, bn,
                       (kb + 2) << 6, J.lda, J.K, J.im2col, lrow, g);
        }
        CP_COMMIT();

        const uint32_t Ab = smem_base + stg * STG_BYTES;
#pragma unroll
        for (int ks = 0; ks < 4; ks++) {
            const uint32_t axor = (uint32_t)((((ks << 1) + a_kq) ^ l7) << 4);
            const uint32_t bxor = (uint32_t)((((ks << 1) + b_kq) ^ l7) << 4);
            uint32_t af[4][4], bf[2][4];
#pragma unroll
            for (int mt = 0; mt < 4; mt++) ldsm4(af[mt], Ab + arow[mt] + axor);
#pragma unroll
            for (int p = 0; p < 2; p++)    ldsm4(bf[p],  Ab + brow[p] + bxor);
#pragma unroll
            for (int mt = 0; mt < 4; mt++) {
                mma16(acc[mt][0], af[mt], &bf[0][0]);
                mma16(acc[mt][1], af[mt], &bf[0][2]);
                mma16(acc[mt][2], af[mt], &bf[1][0]);
                mma16(acc[mt][3], af[mt], &bf[1][2]);
            }
        }
        if (++stg == 3) stg = 0;
    }

    // ---------------- epilogue ----------------
    const bool halfout = (J.mode == 1) || (J.mode == 2) || (J.mode == 3) || (J.mode == 6);
#pragma unroll
    for (int mt = 0; mt < 4; mt++) {
        const int m0 = bm + wm + (mt << 4) + lg;
#pragma unroll
        for (int nt = 0; nt < 4; nt++) {
            const int n = bn + wn + (nt << 3) + (la3 << 1);
            const float b0 = J.bias[n], b1 = J.bias[n + 1];
            float v[4] = {acc[mt][nt].x + b0, acc[mt][nt].y + b1,
                          acc[mt][nt].z + b0, acc[mt][nt].w + b1};
#pragma unroll
            for (int h = 0; h < 2; h++) {
                const int m = m0 + h * 8;
                if (halfout) {
                    float x0 = v[h * 2], x1 = v[h * 2 + 1];
                    if (J.mode == 1) { x0 *= J.scale; x1 *= J.scale; }
                    else if (J.mode == 2) { x0 = fmaxf(x0, 0.f); x1 = fmaxf(x1, 0.f); }
                    else if (J.mode == 3) {
                        x0 = 0.5f * x0 * (1.f + erff(x0 * 0.70710678118654752f));
                        x1 = 0.5f * x1 * (1.f + erff(x1 * 0.70710678118654752f));
                    }
                    *reinterpret_cast<__half2*>(
                        reinterpret_cast<__half*>(J.C) + (size_t)m * (size_t)J.N + n) =
                        __floats2half2_rn(x0, x1);
                } else {
#pragma unroll
                    for (int j = 0; j < 2; j++) {
                        float x = v[h * 2 + j];
                        const int nn = n + j;
                        if (J.mode == 4) x += J.R[((size_t)(m >> 12) * 256 + nn) * 4096 + (m & 4095)];
                        else if (J.mode == 5) x += J.R[(size_t)m * 256 + nn];
                        if (J.mode == 5)
                            J.C[((size_t)(m >> 12) * 256 + nn) * 4096 + (m & 4095)] = x;
                        else
                            J.C[(size_t)m * (size_t)J.N + nn] = x;
                    }
                }
            }
        }
    }
}

// ---------------- offset head (fp16 h1) ----------------
__global__ void off2_k(const __half* __restrict__ h1, const float* __restrict__ w,
                       const float* __restrict__ bias, float* __restrict__ offs) {
    int id = blockIdx.x * blockDim.x + threadIdx.x;
    if (id >= MTOT * 18) return;
    int m = id / 18, n = id - m * 18;
    const uint4* a = reinterpret_cast<const uint4*>(h1 + (size_t)m * 256);
    const float4* ww = reinterpret_cast<const float4*>(w + (size_t)n * 256);
    float s = bias[n];
#pragma unroll 8
    for (int k = 0; k < 32; k++) {
        uint4 av = a[k];
        const __half2* hh = reinterpret_cast<const __half2*>(&av);
        float2 f0 = __half22float2(hh[0]), f1 = __half22float2(hh[1]);
        float2 f2 = __half22float2(hh[2]), f3 = __half22float2(hh[3]);
        float4 w0 = ww[2 * k], w1 = ww[2 * k + 1];
        s += f0.x * w0.x + f0.y * w0.y + f1.x * w0.z + f1.y * w0.w;
        s += f2.x * w1.x + f2.y * w1.y + f3.x * w1.z + f3.y * w1.w;
    }
    offs[id] = s;
}

// ---------------- fused bilinear-sample + 9-way attention (all fp16 in, fp16 out) ----------------
#define LOAD8H(dst, ptr)                                                    \
    {                                                                       \
        uint4 _u = *reinterpret_cast<const uint4*>(ptr);                    \
        __half2* _hh = reinterpret_cast<__half2*>(&_u);                     \
        float2 _f0 = __half22float2(_hh[0]), _f1 = __half22float2(_hh[1]);  \
        float2 _f2 = __half22float2(_hh[2]), _f3 = __half22float2(_hh[3]);  \
        dst[0] = _f0.x; dst[1] = _f0.y; dst[2] = _f1.x; dst[3] = _f1.y;     \
        dst[4] = _f2.x; dst[5] = _f2.y; dst[6] = _f3.x; dst[7] = _f3.y;     \
    }

__global__ void __launch_bounds__(256) attn_k(
    const __half* __restrict__ qb, const __half* __restrict__ kv,
    const float* __restrict__ offs, __half* __restrict__ outp) {
    __shared__ float sh[8][9][8];
    const int warp = threadIdx.x >> 5, lane = threadIdx.x & 31;
    const int p = blockIdx.x * 8 + warp;
    const int b = p >> 12, s = p & 4095, y = s >> 6, x = s & 63;
    const __half* kvb = kv + (((size_t)b << 12) << 9);

    float qr[8];
    LOAD8H(qr, qb + (size_t)p * 256 + lane * 8);

    for (int o = 0; o < 9; o++) {
        int ys = y + o / 3 - 1, xs = x + o % 3 - 1;
        float prod[8] = {0.f, 0.f, 0.f, 0.f, 0.f, 0.f, 0.f, 0.f};
        if (ys >= 0 && ys < 64 && xs >= 0 && xs < 64) {
            const float* op = offs + (size_t)((b << 12) + (ys << 6) + xs) * 18 + 2 * o;
            float px = op[0], py = op[1];
            float y0f = floorf(py), x0f = floorf(px);
            float wy = py - y0f, wx = px - x0f;
            int y0 = (int)y0f, x0 = (int)x0f;
            float w00 = (1.f - wy) * (1.f - wx), w01 = (1.f - wy) * wx;
            float w10 = wy * (1.f - wx), w11 = wy * wx;
            bool vy0 = (y0 >= 0) && (y0 < 64), vy1 = (y0 + 1 >= 0) && (y0 + 1 < 64);
            bool vx0 = (x0 >= 0) && (x0 < 64), vx1 = (x0 + 1 >= 0) && (x0 + 1 < 64);
            w00 = (vy0 && vx0) ? w00 : 0.f; w01 = (vy0 && vx1) ? w01 : 0.f;
            w10 = (vy1 && vx0) ? w10 : 0.f; w11 = (vy1 && vx1) ? w11 : 0.f;
            int y0c = min(max(y0, 0), 63), y1c = min(max(y0 + 1, 0), 63);
            int x0c = min(max(x0, 0), 63), x1c = min(max(x0 + 1, 0), 63);
            float c00[8], c01[8], c10[8], c11[8];
            LOAD8H(c00, kvb + ((size_t)((y0c << 6) + x0c) << 9) + lane * 8);
            LOAD8H(c01, kvb + ((size_t)((y0c << 6) + x1c) << 9) + lane * 8);
            LOAD8H(c10, kvb + ((size_t)((y1c << 6) + x0c) << 9) + lane * 8);
            LOAD8H(c11, kvb + ((size_t)((y1c << 6) + x1c) << 9) + lane * 8);
#pragma unroll
            for (int h = 0; h < 8; h++) {
                float kvv = w00 * c00[h] + w01 * c01[h] + w10 * c10[h] + w11 * c11[h];
                prod[h] = qr[h] * kvv;
            }
        }
#pragma unroll
        for (int off = 16; off > 0; off >>= 1)
#pragma unroll
            for (int h = 0; h < 8; h++)
                prod[h] += __shfl_xor_sync(0xffffffffu, prod[h], off);
        if (lane == 0) {
#pragma unroll
            for (int h = 0; h < 8; h++) sh[warp][o][h] = prod[h];
        }
    }
    __syncwarp();
    if (lane < 8) {
        float e[9]; float mx = -1e30f;
#pragma unroll
        for (int o = 0; o < 9; o++) { e[o] = sh[warp][o][lane]; mx = fmaxf(mx, e[o]); }
        float sm = 0.f;
#pragma unroll
        for (int o = 0; o < 9; o++) { e[o] = expf(e[o] - mx); sm += e[o]; }
        float inv = 1.f / sm;
#pragma unroll
        for (int o = 0; o < 9; o++) sh[warp][o][lane] = e[o] * inv;
    }
    __syncwarp();
    float acc[8] = {0.f, 0.f, 0.f, 0.f, 0.f, 0.f, 0.f, 0.f};
    for (int o = 0; o < 9; o++) {
        int ys = y + o / 3 - 1, xs = x + o % 3 - 1;
        if (ys < 0 || ys >= 64 || xs < 0 || xs >= 64) continue;
        const float* op = offs + (size_t)((b << 12) + (ys << 6) + xs) * 18 + 2 * o;
        float px = op[0], py = op[1];
        float y0f = floorf(py), x0f = floorf(px);
        float wy = py - y0f, wx = px - x0f;
        int y0 = (int)y0f, x0 = (int)x0f;
        float w00 = (1.f - wy) * (1.f - wx), w01 = (1.f - wy) * wx;
        float w10 = wy * (1.f - wx), w11 = wy * wx;
        bool vy0 = (y0 >= 0) && (y0 < 64), vy1 = (y0 + 1 >= 0) && (y0 + 1 < 64);
        bool vx0 = (x0 >= 0) && (x0 < 64), vx1 = (x0 + 1 >= 0) && (x0 + 1 < 64);
        w00 = (vy0 && vx0) ? w00 : 0.f; w01 = (vy0 && vx1) ? w01 : 0.f;
        w10 = (vy1 && vx0) ? w10 : 0.f; w11 = (vy1 && vx1) ? w11 : 0.f;
        int y0c = min(max(y0, 0), 63), y1c = min(max(y0 + 1, 0), 63);
        int x0c = min(max(x0, 0), 63), x1c = min(max(x0 + 1, 0), 63);
        float c00[8], c01[8], c10[8], c11[8];
        LOAD8H(c00, kvb + ((size_t)((y0c << 6) + x0c) << 9) + 256 + lane * 8);
        LOAD8H(c01, kvb + ((size_t)((y0c << 6) + x1c) << 9) + 256 + lane * 8);
        LOAD8H(c10, kvb + ((size_t)((y1c << 6) + x0c) << 9) + 256 + lane * 8);
        LOAD8H(c11, kvb + ((size_t)((y1c << 6) + x1c) << 9) + 256 + lane * 8);
#pragma unroll
        for (int h = 0; h < 8; h++) {
            float vv = w00 * c00[h] + w01 * c01[h] + w10 * c10[h] + w11 * c11[h];
            acc[h] += sh[warp][o][h] * vv;
        }
    }
    __half2 h0 = __floats2half2_rn(acc[0], acc[1]);
    __half2 h1 = __floats2half2_rn(acc[2], acc[3]);
    __half2 h2 = __floats2half2_rn(acc[4], acc[5]);
    __half2 h3 = __floats2half2_rn(acc[6], acc[7]);
    uint4 pk;
    pk.x = *reinterpret_cast<uint32_t*>(&h0);
    pk.y = *reinterpret_cast<uint32_t*>(&h1);
    pk.z = *reinterpret_cast<uint32_t*>(&h2);
    pk.w = *reinterpret_cast<uint32_t*>(&h3);
    *reinterpret_cast<uint4*>(outp + (size_t)p * 256 + lane * 8) = pk;
}

// ---------------- host ----------------
extern "C" void kernel_launch(void* const* d_in, const int* in_sizes, int n_in,
                              void* d_out, int out_size) {
    const float* x_q    = (const float*)d_in[0];
    const float* x_kv   = (const float*)d_in[1];
    const float* n1w    = (const float*)d_in[2];
    const float* n1b    = (const float*)d_in[3];
    const float* q_w    = (const float*)d_in[4];
    const float* q_b    = (const float*)d_in[5];
    const float* kv_w   = (const float*)d_in[6];
    const float* kv_b   = (const float*)d_in[7];
    const float* off1_w = (const float*)d_in[8];
    const float* off1_b = (const float*)d_in[9];
    const float* off2_w = (const float*)d_in[10];
    const float* off2_b = (const float*)d_in[11];
    const float* proj_w = (const float*)d_in[12];
    const float* proj_b = (const float*)d_in[13];
    const float* n2w    = (const float*)d_in[14];
    const float* n2b    = (const float*)d_in[15];
    const float* fc1_w  = (const float*)d_in[16];
    const float* fc1_b  = (const float*)d_in[17];
    const float* fc2_w  = (const float*)d_in[18];
    const float* fc2_b  = (const float*)d_in[19];
    float* out = (float*)d_out;

    __half *xall, *qb, *kvb, *h1, *att, *xn2, *hid, *wr, *wh;
    float *offs, *xres, *st1, *st2;
    float2* part;
    cudaGetSymbolAddress((void**)&xall, g_xall);
    cudaGetSymbolAddress((void**)&qb,   g_q);
    cudaGetSymbolAddress((void**)&kvb,  g_kv);
    cudaGetSymbolAddress((void**)&h1,   g_h1);
    cudaGetSymbolAddress((void**)&offs, g_offs);
    cudaGetSymbolAddress((void**)&att,  g_att);
    cudaGetSymbolAddress((void**)&xres, g_xres);
    cudaGetSymbolAddress((void**)&xn2,  g_xn2);
    cudaGetSymbolAddress((void**)&hid,  g_hid);
    cudaGetSymbolAddress((void**)&wr,   g_wr);
    cudaGetSymbolAddress((void**)&wh,   g_wh);
    cudaGetSymbolAddress((void**)&part, g_part);
    cudaGetSymbolAddress((void**)&st1,  g_st1);
    cudaGetSymbolAddress((void**)&st2,  g_st2);

    __half* qwh  = wh;
    __half* kvwh = qwh  + 65536;
    __half* pwh  = kvwh + 131072;
    __half* f1wh = pwh  + 65536;
    __half* f2wh = f1wh + 262144;

    cudaFuncSetAttribute(gemm_tc, cudaFuncAttributeMaxDynamicSharedMemorySize, SMEM_REQ);

    prep_k<<<7680, 256>>>(off1_w, wr, q_w, qwh, kv_w, kvwh, proj_w, pwh,
                          fc1_w, f1wh, fc2_w, f2wh);
    gn_p1<<<256, 256>>>(x_q, x_kv, part);
    gn_p2<<<1, 256>>>(part, st1, 8);
    norm_pack_k<<<dim3(128, 8, 8), dim3(32, 8)>>>(x_q, x_kv, st1, n1w, n1b, xall);

    GJob zero = {};
    // fused q + kv + conv (conv first)
    {
        GJob jc  = {xall,       wr,   off1_b, (float*)h1,  nullptr, 256, 4608, 512, 2, 1, 0.f};
        GJob jkv = {xall + 256, kvwh, kv_b,   (float*)kvb, nullptr, 512, 256,  512, 6, 0, 0.f};
        GJob jq  = {xall,       qwh,  q_b,    (float*)qb,  nullptr, 256, 256,  512, 1, 0,
                    0.17677669529663689f};
        gemm_tc<<<1024, 256, SMEM_REQ>>>(jc, jkv, jq, 256, 768);
    }
    off2_k<<<(MTOT * 18) / 256, 256>>>(h1, off2_w, off2_b, offs);
    attn_k<<<2048, 256>>>(qb, kvb, offs, att);
    // xres = x_q + att @ proj_w^T + b
    {
        GJob jp = {att, pwh, proj_b, xres, x_q, 256, 256, 256, 4, 0, 0.f};
        gemm_tc<<<256, 256, SMEM_REQ>>>(jp, zero, zero, 256, 256);
    }
    gn_p1<<<128, 256>>>(xres, xres, part);
    gn_p2<<<1, 256>>>(part, st2, 4);
    norm2_k<<<(MTOT * 256) / 256, 256>>>(xres, st2, n2w, n2b, xn2);
    // hid = gelu(xn2 @ fc1_w^T + b) -> half
    {
        GJob jf1 = {xn2, f1wh, fc1_b, (float*)hid, nullptr, 1024, 256, 256, 3, 0, 0.f};
        gemm_tc<<<1024, 256, SMEM_REQ>>>(jf1, zero, zero, 1024, 1024);
    }
    // out(NCHW) = xres + hid @ fc2_w^T + b   (256 CTAs)
    {
        GJob jf2 = {hid, f2wh, fc2_b, out, xres, 256, 1024, 1024, 5, 0, 0.f};
        gemm_tc<<<256, 256, SMEM_REQ>>>(jf2, zero, zero, 256, 256);
    }
}

// round 12
// speedup vs baseline: 1.0885x; 1.0885x over previous
#include <cuda_runtime.h>
#include <cuda_fp16.h>
#include <math.h>
#include <stdint.h>

#define MTOT 16384

// ---------------- scratch ----------------
__device__ __align__(1024) __half g_xall[(size_t)MTOT * 512];
__device__ __align__(1024) __half g_q   [(size_t)MTOT * 256];
__device__ __align__(1024) __half g_kv  [(size_t)MTOT * 512];
__device__ __align__(1024) __half g_h1  [(size_t)MTOT * 256];
__device__ __align__(1024) __half g_U   [(size_t)65536 * 512];   // winograd input  [s][tile][c]
__device__ __align__(1024) __half g_V   [(size_t)65536 * 256];   // winograd output [s][tile][o]
__device__ float  g_offs[(size_t)MTOT * 18];
__device__ __align__(1024) __half g_att [(size_t)MTOT * 256];
__device__ float  g_xres[(size_t)MTOT * 256];
__device__ __align__(1024) __half g_xn2 [(size_t)MTOT * 256];
__device__ __align__(1024) __half g_hid [(size_t)MTOT * 1024];
__device__ __align__(1024) __half g_wrw [16 * 256 * 512];        // winograd weights [s][o][c]
__device__ __align__(1024) __half g_wh  [65536 + 131072 + 65536 + 262144 + 262144];
__device__ float  g_zero[256];                                    // stays 0 (never written)
__device__ float2 g_part[256];
__device__ float  g_st1 [16];
__device__ float  g_st2 [8];

// ---------------- fused weight prep: winograd transform + 5x f2h ----------------
// ranges: wino 131072 | q 65536 | kv 131072 | proj 65536 | fc1 262144 | fc2 262144
__global__ void prep_k(const float* __restrict__ off1_w, __half* __restrict__ wrw,
                       const float* __restrict__ q_w,    __half* __restrict__ qwh,
                       const float* __restrict__ kv_w,   __half* __restrict__ kvwh,
                       const float* __restrict__ proj_w, __half* __restrict__ pwh,
                       const float* __restrict__ fc1_w,  __half* __restrict__ f1wh,
                       const float* __restrict__ fc2_w,  __half* __restrict__ f2wh) {
    int id = blockIdx.x * 256 + threadIdx.x;
    if (id < 131072) {
        int o = id >> 9, c = id & 511;
        const float* g = off1_w + (size_t)(o * 512 + c) * 9;
        float r[4][3];
#pragma unroll
        for (int j = 0; j < 3; j++) {
            float g0 = g[j], g1 = g[3 + j], g2 = g[6 + j];
            r[0][j] = g0;
            r[1][j] = 0.5f * (g0 + g1 + g2);
            r[2][j] = 0.5f * (g0 - g1 + g2);
            r[3][j] = g2;
        }
#pragma unroll
        for (int i = 0; i < 4; i++) {
            float w0 = r[i][0], w1 = 0.5f * (r[i][0] + r[i][1] + r[i][2]);
            float w2 = 0.5f * (r[i][0] - r[i][1] + r[i][2]), w3 = r[i][2];
            wrw[(((size_t)(i * 4 + 0) * 256 + o) << 9) + c] = __float2half(w0);
            wrw[(((size_t)(i * 4 + 1) * 256 + o) << 9) + c] = __float2half(w1);
            wrw[(((size_t)(i * 4 + 2) * 256 + o) << 9) + c] = __float2half(w2);
            wrw[(((size_t)(i * 4 + 3) * 256 + o) << 9) + c] = __float2half(w3);
        }
        return;
    }
    id -= 131072;
    if (id < 65536)  { qwh [id] = __float2half(q_w [id]); return; }  id -= 65536;
    if (id < 131072) { kvwh[id] = __float2half(kv_w[id]); return; }  id -= 131072;
    if (id < 65536)  { pwh [id] = __float2half(proj_w[id]); return; } id -= 65536;
    if (id < 262144) { f1wh[id] = __float2half(fc1_w[id]); return; }  id -= 262144;
    f2wh[id] = __float2half(fc2_w[id]);
}

// ---------------- winograd input transform: xall -> U[s][tile][c], 2 ch/thread ----------------
__global__ void wino_in_k(const __half* __restrict__ xall, __half* __restrict__ U) {
    int id = blockIdx.x * 256 + threadIdx.x;     // 4096 tiles * 256 ch-pairs = 1048576
    int c2 = id & 255, t = id >> 8;
    int c = c2 << 1;
    int b = t >> 10, sp = t & 1023, ty = sp >> 5, tx = sp & 31;
    int y0 = (ty << 1) - 1, x0 = (tx << 1) - 1;
    float d0[4][4], d1[4][4];
#pragma unroll
    for (int i = 0; i < 4; i++) {
        int yy = y0 + i;
#pragma unroll
        for (int j = 0; j < 4; j++) {
            int xx = x0 + j;
            if (yy >= 0 && yy < 64 && xx >= 0 && xx < 64) {
                uint32_t v = *reinterpret_cast<const uint32_t*>(
                    xall + (((size_t)(b << 12) + (yy << 6) + xx) << 9) + c);
                float2 f = __half22float2(*reinterpret_cast<__half2*>(&v));
                d0[i][j] = f.x; d1[i][j] = f.y;
            } else { d0[i][j] = 0.f; d1[i][j] = 0.f; }
        }
    }
    float t0[4][4], t1[4][4];
#pragma unroll
    for (int j = 0; j < 4; j++) {
        t0[0][j] = d0[0][j] - d0[2][j]; t1[0][j] = d1[0][j] - d1[2][j];
        t0[1][j] = d0[1][j] + d0[2][j]; t1[1][j] = d1[1][j] + d1[2][j];
        t0[2][j] = d0[2][j] - d0[1][j]; t1[2][j] = d1[2][j] - d1[1][j];
        t0[3][j] = d0[1][j] - d0[3][j]; t1[3][j] = d1[1][j] - d1[3][j];
    }
#pragma unroll
    for (int i = 0; i < 4; i++) {
        float u0[4], u1[4];
        u0[0] = t0[i][0] - t0[i][2]; u1[0] = t1[i][0] - t1[i][2];
        u0[1] = t0[i][1] + t0[i][2]; u1[1] = t1[i][1] + t1[i][2];
        u0[2] = t0[i][2] - t0[i][1]; u1[2] = t1[i][2] - t1[i][1];
        u0[3] = t0[i][1] - t0[i][3]; u1[3] = t1[i][1] - t1[i][3];
#pragma unroll
        for (int j = 0; j < 4; j++) {
            __half2 hv = __floats2half2_rn(u0[j], u1[j]);
            *reinterpret_cast<uint32_t*>(
                U + (((size_t)(i * 4 + j) * 4096 + t) << 9) + c) =
                *reinterpret_cast<uint32_t*>(&hv);
        }
    }
}

// ---------------- winograd output transform: V -> h1 (bias + relu), 2 ch/thread ----------------
__global__ void wino_out_k(const __half* __restrict__ V, const float* __restrict__ bias,
                           __half* __restrict__ h1) {
    int id = blockIdx.x * 256 + threadIdx.x;     // 4096 tiles * 128 o-pairs = 524288
    int o2 = id & 127, t = id >> 7;
    int o = o2 << 1;
    int b = t >> 10, sp = t & 1023, ty = sp >> 5, tx = sp & 31;
    float m0[4][4], m1[4][4];
#pragma unroll
    for (int i = 0; i < 4; i++)
#pragma unroll
        for (int j = 0; j < 4; j++) {
            uint32_t v = *reinterpret_cast<const uint32_t*>(
                V + (((size_t)(i * 4 + j) * 4096 + t) << 8) + o);
            float2 f = __half22float2(*reinterpret_cast<__half2*>(&v));
            m0[i][j] = f.x; m1[i][j] = f.y;
        }
    float b0 = bias[o], b1 = bias[o + 1];
    float p00[4], p01[4], p10[4], p11[4];
#pragma unroll
    for (int j = 0; j < 4; j++) {
        p00[j] = m0[0][j] + m0[1][j] + m0[2][j];
        p01[j] = m0[1][j] - m0[2][j] - m0[3][j];
        p10[j] = m1[0][j] + m1[1][j] + m1[2][j];
        p11[j] = m1[1][j] - m1[2][j] - m1[3][j];
    }
    float y0[2][2], y1[2][2];
    y0[0][0] = p00[0] + p00[1] + p00[2];  y0[0][1] = p00[1] - p00[2] - p00[3];
    y0[1][0] = p01[0] + p01[1] + p01[2];  y0[1][1] = p01[1] - p01[2] - p01[3];
    y1[0][0] = p10[0] + p10[1] + p10[2];  y1[0][1] = p10[1] - p10[2] - p10[3];
    y1[1][0] = p11[0] + p11[1] + p11[2];  y1[1][1] = p11[1] - p11[2] - p11[3];
#pragma unroll
    for (int r = 0; r < 2; r++)
#pragma unroll
        for (int cc = 0; cc < 2; cc++) {
            float v0 = fmaxf(y0[r][cc] + b0, 0.f);
            float v1 = fmaxf(y1[r][cc] + b1, 0.f);
            __half2 hv = __floats2half2_rn(v0, v1);
            int py = (ty << 1) + r, px = (tx << 1) + cc;
            *reinterpret_cast<uint32_t*>(
                h1 + (((size_t)(b << 12) + (py << 6) + px) << 8) + o) =
                *reinterpret_cast<uint32_t*>(&hv);
        }
}

// ---------------- groupnorm stats: phase 1 ----------------
__global__ void gn_p1(const float* __restrict__ A, const float* __restrict__ B2,
                      float2* __restrict__ part) {
    int bi = blockIdx.x;
    int slab = bi >> 5, chunk = bi & 31;
    int tensor = slab >> 2, batch = slab & 3;
    const float* src = (tensor ? B2 : A) + ((size_t)batch << 20) + ((size_t)chunk << 15);
    const float4* p4 = reinterpret_cast<const float4*>(src);
    float s = 0.f, s2 = 0.f;
    for (int i = threadIdx.x; i < 8192; i += 256) {
        float4 v = p4[i];
        s  += v.x + v.y + v.z + v.w;
        s2 += v.x * v.x + v.y * v.y + v.z * v.z + v.w * v.w;
    }
    __shared__ float sh1[256], sh2[256];
    sh1[threadIdx.x] = s; sh2[threadIdx.x] = s2;
    __syncthreads();
    for (int st = 128; st > 0; st >>= 1) {
        if (threadIdx.x < st) { sh1[threadIdx.x] += sh1[threadIdx.x + st];
                                sh2[threadIdx.x] += sh2[threadIdx.x + st]; }
        __syncthreads();
    }
    if (threadIdx.x == 0) part[slab * 32 + chunk] = make_float2(sh1[0], sh2[0]);
}

// ---------------- groupnorm stats: phase 2 ----------------
__global__ void gn_p2(const float2* __restrict__ part, float* __restrict__ stats, int nslab) {
    int slab = threadIdx.x >> 5, lane = threadIdx.x & 31;
    if (slab >= nslab) return;
    float2 v = part[slab * 32 + lane];
    float s = v.x, s2 = v.y;
#pragma unroll
    for (int off = 16; off > 0; off >>= 1) {
        s  += __shfl_xor_sync(0xffffffffu, s,  off);
        s2 += __shfl_xor_sync(0xffffffffu, s2, off);
    }
    if (lane == 0) {
        float inv = 1.f / 1048576.f;
        float mu = s * inv;
        float var = s2 * inv - mu * mu;
        stats[slab * 2] = mu;
        stats[slab * 2 + 1] = rsqrtf(var + 1e-5f);
    }
}

// ---------------- normalize + NCHW->NHWC pack (fp16 out) ----------------
__global__ void norm_pack_k(const float* __restrict__ xq, const float* __restrict__ xkv,
                            const float* __restrict__ stats, const float* __restrict__ w,
                            const float* __restrict__ bb, __half* __restrict__ xall) {
    __shared__ float tile[32][33];
    int bz = blockIdx.z;
    int tensor = bz >> 2, batch = bz & 3;
    const float* src = (tensor == 0 ? xq : xkv) + ((size_t)batch << 20);
    float mu = stats[bz * 2], rstd = stats[bz * 2 + 1];
    int s0 = blockIdx.x * 32, c0 = blockIdx.y * 32;
    int tx = threadIdx.x, ty = threadIdx.y;
#pragma unroll
    for (int k = 0; k < 4; k++) {
        int c = c0 + ty + k * 8;
        tile[ty + k * 8][tx] = src[(size_t)c * 4096 + s0 + tx];
    }
    __syncthreads();
#pragma unroll
    for (int k = 0; k < 4; k++) {
        int sl = ty + k * 8;
        int c = c0 + tx;
        float v = (tile[tx][sl] - mu) * rstd * w[c] + bb[c];
        xall[(((size_t)batch * 4096 + s0 + sl) << 9) + tensor * 256 + c] = __float2half(v);
    }
}

// ---------------- norm2 (fp16 out) ----------------
__global__ void norm2_k(const float* __restrict__ xres, const float* __restrict__ stats,
                        const float* __restrict__ w, const float* __restrict__ bb,
                        __half* __restrict__ xn) {
    int id = blockIdx.x * blockDim.x + threadIdx.x;
    if (id >= MTOT * 256) return;
    int b = id >> 20, c = id & 255;
    xn[id] = __float2half((xres[id] - stats[b * 2]) * stats[b * 2 + 1] * w[c] + bb[c]);
}

// ---------------- PTX helpers ----------------
__device__ __forceinline__ void mma16(float4& d, const uint32_t* a, const uint32_t* b) {
    asm volatile("mma.sync.aligned.m16n8k16.row.col.f32.f16.f16.f32 "
        "{%0,%1,%2,%3}, {%4,%5,%6,%7}, {%8,%9}, {%0,%1,%2,%3};\n"
        : "+f"(d.x), "+f"(d.y), "+f"(d.z), "+f"(d.w)
        : "r"(a[0]), "r"(a[1]), "r"(a[2]), "r"(a[3]), "r"(b[0]), "r"(b[1]));
}
__device__ __forceinline__ void ldsm4(uint32_t* r, uint32_t a) {
    asm volatile("ldmatrix.sync.aligned.m8n8.x4.shared.b16 {%0,%1,%2,%3}, [%4];"
        : "=r"(r[0]), "=r"(r[1]), "=r"(r[2]), "=r"(r[3]) : "r"(a));
}
__device__ __forceinline__ void cp16(uint32_t d, const void* s, int sz) {
    asm volatile("cp.async.cg.shared.global [%0], [%1], 16, %2;"
        :: "r"(d), "l"(s), "r"(sz));
}
#define CP_COMMIT() asm volatile("cp.async.commit_group;")

// ---------------- multi-job fp16 tensor-core GEMM ----------------
// C[M,N] = A[M,K] @ W[N,K]^T + bias (A, W fp16; accum/bias fp32).
// half-out modes: 1 *scale  2 relu  3 gelu  6 plain
// fp32 modes:     4 +R(NCHW)->NHWC  5 +R(NHWC)->NCHW
// wino flag: W advanced by (bm>>12)*131072 (per-slice weights)
// CTA tile 128x128x64(halves), 256 thr, 3-stage cp.async, mma m16n8k16, 2 CTA/SM.
#define STG_BYTES 32768
#define SMEM_REQ  (3 * STG_BYTES)

struct GJob {
    const __half* A; const __half* W; const float* bias; float* C; const float* R;
    int N, K, lda, mode, wino; float scale;
};

__device__ __forceinline__ void issue_tile(
    uint32_t sa0, const __half* __restrict__ A, const __half* __restrict__ W,
    int bm, int bn, int K0, int lda, int K, int lrow, int g)
{
    uint32_t sa = sa0 + lrow * 128;
    const __half* srcA = A + (size_t)(bm + lrow) * lda + K0;
    const __half* srcB = W + (size_t)(bn + lrow) * (size_t)K + K0;
    const int r7 = lrow & 7;
#pragma unroll
    for (int j = 0; j < 4; j++) {
        const int c = g + j;
        const uint32_t off = (uint32_t)((c ^ r7) << 4);
        cp16(sa + off, srcA + c * 8, 16);
        cp16(sa + 16384 + off, srcB + c * 8, 16);
    }
}

__global__ void __launch_bounds__(256, 2) gemm_tc(
    GJob j0, GJob j1, GJob j2, int c0, int c1)
{
    extern __shared__ float smbuf[];
    const uint32_t smem_base = (uint32_t)__cvta_generic_to_shared(smbuf);

    GJob J;
    int local;
    {
        const int id = blockIdx.x;
        if (id < c0)      { J = j0; local = id; }
        else if (id < c1) { J = j1; local = id - c0; }
        else              { J = j2; local = id - c1; }
    }
    const int bnb = J.N >> 7;
    const int bm = (local / bnb) << 7, bn = (local % bnb) << 7;
    if (J.wino) J.W += ((size_t)(bm >> 12)) << 17;   // per-slice weights (256*512)

    const int tid  = threadIdx.x;
    const int warp = tid >> 5, lane = tid & 31;
    const int wm   = (warp >> 2) << 6, wn = (warp & 3) << 5;
    const int lg   = lane >> 2, la3 = lane & 3;

    const int lrow = tid >> 1, g = (tid & 1) * 4;

    const int l7 = lane & 7, lq = lane >> 3;
    uint32_t arow[4], brow[2];
#pragma unroll
    for (int mt = 0; mt < 4; mt++)
        arow[mt] = (uint32_t)((wm + mt * 16 + ((lq & 1) << 3) + l7) * 128);
    const int a_kq = lq >> 1;
#pragma unroll
    for (int p = 0; p < 2; p++)
        brow[p] = (uint32_t)(16384 + (wn + p * 16 + ((lq >> 1) << 3) + l7) * 128);
    const int b_kq = lq & 1;

    float4 acc[4][4];
#pragma unroll
    for (int i = 0; i < 4; i++)
#pragma unroll
        for (int j = 0; j < 4; j++) acc[i][j] = make_float4(0.f, 0.f, 0.f, 0.f);

    const int nkb = J.K >> 6;
    issue_tile(smem_base,             J.A, J.W, bm, bn,  0, J.lda, J.K, lrow, g);
    CP_COMMIT();
    issue_tile(smem_base + STG_BYTES, J.A, J.W, bm, bn, 64, J.lda, J.K, lrow, g);
    CP_COMMIT();

    int stg = 0;
    for (int kb = 0; kb < nkb; kb++) {
        asm volatile("cp.async.wait_group 1;");
        __syncthreads();
        if (kb + 2 < nkb) {
            int s2 = stg + 2; if (s2 >= 3) s2 -= 3;
            issue_tile(smem_base + s2 * STG_BYTES, J.A, J.W, bm, bn,
                       (kb + 2) << 6, J.lda, J.K, lrow, g);
        }
        CP_COMMIT();

        const uint32_t Ab = smem_base + stg * STG_BYTES;
#pragma unroll
        for (int ks = 0; ks < 4; ks++) {
            const uint32_t axor = (uint32_t)((((ks << 1) + a_kq) ^ l7) << 4);
            const uint32_t bxor = (uint32_t)((((ks << 1) + b_kq) ^ l7) << 4);
            uint32_t af[4][4], bf[2][4];
#pragma unroll
            for (int mt = 0; mt < 4; mt++) ldsm4(af[mt], Ab + arow[mt] + axor);
#pragma unroll
            for (int p = 0; p < 2; p++)    ldsm4(bf[p],  Ab + brow[p] + bxor);
#pragma unroll
            for (int mt = 0; mt < 4; mt++) {
                mma16(acc[mt][0], af[mt], &bf[0][0]);
                mma16(acc[mt][1], af[mt], &bf[0][2]);
                mma16(acc[mt][2], af[mt], &bf[1][0]);
                mma16(acc[mt][3], af[mt], &bf[1][2]);
            }
        }
        if (++stg == 3) stg = 0;
    }

    // ---------------- epilogue ----------------
    const bool halfout = (J.mode == 1) || (J.mode == 2) || (J.mode == 3) || (J.mode == 6);
#pragma unroll
    for (int mt = 0; mt < 4; mt++) {
        const int m0 = bm + wm + (mt << 4) + lg;
#pragma unroll
        for (int nt = 0; nt < 4; nt++) {
            const int n = bn + wn + (nt << 3) + (la3 << 1);
            const float b0 = J.bias[n], b1 = J.bias[n + 1];
            float v[4] = {acc[mt][nt].x + b0, acc[mt][nt].y + b1,
                          acc[mt][nt].z + b0, acc[mt][nt].w + b1};
#pragma unroll
            for (int h = 0; h < 2; h++) {
                const int m = m0 + h * 8;
                if (halfout) {
                    float x0 = v[h * 2], x1 = v[h * 2 + 1];
                    if (J.mode == 1) { x0 *= J.scale; x1 *= J.scale; }
                    else if (J.mode == 2) { x0 = fmaxf(x0, 0.f); x1 = fmaxf(x1, 0.f); }
                    else if (J.mode == 3) {
                        x0 = 0.5f * x0 * (1.f + erff(x0 * 0.70710678118654752f));
                        x1 = 0.5f * x1 * (1.f + erff(x1 * 0.70710678118654752f));
                    }
                    *reinterpret_cast<__half2*>(
                        reinterpret_cast<__half*>(J.C) + (size_t)m * (size_t)J.N + n) =
                        __floats2half2_rn(x0, x1);
                } else {
#pragma unroll
                    for (int j = 0; j < 2; j++) {
                        float x = v[h * 2 + j];
                        const int nn = n + j;
                        if (J.mode == 4) x += J.R[((size_t)(m >> 12) * 256 + nn) * 4096 + (m & 4095)];
                        else if (J.mode == 5) x += J.R[(size_t)m * 256 + nn];
                        if (J.mode == 5)
                            J.C[((size_t)(m >> 12) * 256 + nn) * 4096 + (m & 4095)] = x;
                        else
                            J.C[(size_t)m * (size_t)J.N + nn] = x;
                    }
                }
            }
        }
    }
}

// ---------------- offset head (fp16 h1) ----------------
__global__ void off2_k(const __half* __restrict__ h1, const float* __restrict__ w,
                       const float* __restrict__ bias, float* __restrict__ offs) {
    int id = blockIdx.x * blockDim.x + threadIdx.x;
    if (id >= MTOT * 18) return;
    int m = id / 18, n = id - m * 18;
    const uint4* a = reinterpret_cast<const uint4*>(h1 + (size_t)m * 256);
    const float4* ww = reinterpret_cast<const float4*>(w + (size_t)n * 256);
    float s = bias[n];
#pragma unroll 8
    for (int k = 0; k < 32; k++) {
        uint4 av = a[k];
        const __half2* hh = reinterpret_cast<const __half2*>(&av);
        float2 f0 = __half22float2(hh[0]), f1 = __half22float2(hh[1]);
        float2 f2 = __half22float2(hh[2]), f3 = __half22float2(hh[3]);
        float4 w0 = ww[2 * k], w1 = ww[2 * k + 1];
        s += f0.x * w0.x + f0.y * w0.y + f1.x * w0.z + f1.y * w0.w;
        s += f2.x * w1.x + f2.y * w1.y + f3.x * w1.z + f3.y * w1.w;
    }
    offs[id] = s;
}

// ---------------- fused bilinear-sample + 9-way attention (fp16) ----------------
#define LOAD8H(dst, ptr)                                                    \
    {                                                                       \
        uint4 _u = *reinterpret_cast<const uint4*>(ptr);                    \
        __half2* _hh = reinterpret_cast<__half2*>(&_u);                     \
        float2 _f0 = __half22float2(_hh[0]), _f1 = __half22float2(_hh[1]);  \
        float2 _f2 = __half22float2(_hh[2]), _f3 = __half22float2(_hh[3]);  \
        dst[0] = _f0.x; dst[1] = _f0.y; dst[2] = _f1.x; dst[3] = _f1.y;     \
        dst[4] = _f2.x; dst[5] = _f2.y; dst[6] = _f3.x; dst[7] = _f3.y;     \
    }

__global__ void __launch_bounds__(256) attn_k(
    const __half* __restrict__ qb, const __half* __restrict__ kv,
    const float* __restrict__ offs, __half* __restrict__ outp) {
    __shared__ float sh[8][9][8];
    const int warp = threadIdx.x >> 5, lane = threadIdx.x & 31;
    const int p = blockIdx.x * 8 + warp;
    const int b = p >> 12, s = p & 4095, y = s >> 6, x = s & 63;
    const __half* kvb = kv + (((size_t)b << 12) << 9);

    float qr[8];
    LOAD8H(qr, qb + (size_t)p * 256 + lane * 8);

    for (int o = 0; o < 9; o++) {
        int ys = y + o / 3 - 1, xs = x + o % 3 - 1;
        float prod[8] = {0.f, 0.f, 0.f, 0.f, 0.f, 0.f, 0.f, 0.f};
        if (ys >= 0 && ys < 64 && xs >= 0 && xs < 64) {
            const float* op = offs + (size_t)((b << 12) + (ys << 6) + xs) * 18 + 2 * o;
            float px = op[0], py = op[1];
            float y0f = floorf(py), x0f = floorf(px);
            float wy = py - y0f, wx = px - x0f;
            int y0 = (int)y0f, x0 = (int)x0f;
            float w00 = (1.f - wy) * (1.f - wx), w01 = (1.f - wy) * wx;
            float w10 = wy * (1.f - wx), w11 = wy * wx;
            bool vy0 = (y0 >= 0) && (y0 < 64), vy1 = (y0 + 1 >= 0) && (y0 + 1 < 64);
            bool vx0 = (x0 >= 0) && (x0 < 64), vx1 = (x0 + 1 >= 0) && (x0 + 1 < 64);
            w00 = (vy0 && vx0) ? w00 : 0.f; w01 = (vy0 && vx1) ? w01 : 0.f;
            w10 = (vy1 && vx0) ? w10 : 0.f; w11 = (vy1 && vx1) ? w11 : 0.f;
            int y0c = min(max(y0, 0), 63), y1c = min(max(y0 + 1, 0), 63);
            int x0c = min(max(x0, 0), 63), x1c = min(max(x0 + 1, 0), 63);
            float c00[8], c01[8], c10[8], c11[8];
            LOAD8H(c00, kvb + ((size_t)((y0c << 6) + x0c) << 9) + lane * 8);
            LOAD8H(c01, kvb + ((size_t)((y0c << 6) + x1c) << 9) + lane * 8);
            LOAD8H(c10, kvb + ((size_t)((y1c << 6) + x0c) << 9) + lane * 8);
            LOAD8H(c11, kvb + ((size_t)((y1c << 6) + x1c) << 9) + lane * 8);
#pragma unroll
            for (int h = 0; h < 8; h++) {
                float kvv = w00 * c00[h] + w01 * c01[h] + w10 * c10[h] + w11 * c11[h];
                prod[h] = qr[h] * kvv;
            }
        }
#pragma unroll
        for (int off = 16; off > 0; off >>= 1)
#pragma unroll
            for (int h = 0; h < 8; h++)
                prod[h] += __shfl_xor_sync(0xffffffffu, prod[h], off);
        if (lane == 0) {
#pragma unroll
            for (int h = 0; h < 8; h++) sh[warp][o][h] = prod[h];
        }
    }
    __syncwarp();
    if (lane < 8) {
        float e[9]; float mx = -1e30f;
#pragma unroll
        for (int o = 0; o < 9; o++) { e[o] = sh[warp][o][lane]; mx = fmaxf(mx, e[o]); }
        float sm = 0.f;
#pragma unroll
        for (int o = 0; o < 9; o++) { e[o] = expf(e[o] - mx); sm += e[o]; }
        float inv = 1.f / sm;
#pragma unroll
        for (int o = 0; o < 9; o++) sh[warp][o][lane] = e[o] * inv;
    }
    __syncwarp();
    float acc[8] = {0.f, 0.f, 0.f, 0.f, 0.f, 0.f, 0.f, 0.f};
    for (int o = 0; o < 9; o++) {
        int ys = y + o / 3 - 1, xs = x + o % 3 - 1;
        if (ys < 0 || ys >= 64 || xs < 0 || xs >= 64) continue;
        const float* op = offs + (size_t)((b << 12) + (ys << 6) + xs) * 18 + 2 * o;
        float px = op[0], py = op[1];
        float y0f = floorf(py), x0f = floorf(px);
        float wy = py - y0f, wx = px - x0f;
        int y0 = (int)y0f, x0 = (int)x0f;
        float w00 = (1.f - wy) * (1.f - wx), w01 = (1.f - wy) * wx;
        float w10 = wy * (1.f - wx), w11 = wy * wx;
        bool vy0 = (y0 >= 0) && (y0 < 64), vy1 = (y0 + 1 >= 0) && (y0 + 1 < 64);
        bool vx0 = (x0 >= 0) && (x0 < 64), vx1 = (x0 + 1 >= 0) && (x0 + 1 < 64);
        w00 = (vy0 && vx0) ? w00 : 0.f; w01 = (vy0 && vx1) ? w01 : 0.f;
        w10 = (vy1 && vx0) ? w10 : 0.f; w11 = (vy1 && vx1) ? w11 : 0.f;
        int y0c = min(max(y0, 0), 63), y1c = min(max(y0 + 1, 0), 63);
        int x0c = min(max(x0, 0), 63), x1c = min(max(x0 + 1, 0), 63);
        float c00[8], c01[8], c10[8], c11[8];
        LOAD8H(c00, kvb + ((size_t)((y0c << 6) + x0c) << 9) + 256 + lane * 8);
        LOAD8H(c01, kvb + ((size_t)((y0c << 6) + x1c) << 9) + 256 + lane * 8);
        LOAD8H(c10, kvb + ((size_t)((y1c << 6) + x0c) << 9) + 256 + lane * 8);
        LOAD8H(c11, kvb + ((size_t)((y1c << 6) + x1c) << 9) + 256 + lane * 8);
#pragma unroll
        for (int h = 0; h < 8; h++) {
            float vv = w00 * c00[h] + w01 * c01[h] + w10 * c10[h] + w11 * c11[h];
            acc[h] += sh[warp][o][h] * vv;
        }
    }
    __half2 h0 = __floats2half2_rn(acc[0], acc[1]);
    __half2 h1 = __floats2half2_rn(acc[2], acc[3]);
    __half2 h2 = __floats2half2_rn(acc[4], acc[5]);
    __half2 h3 = __floats2half2_rn(acc[6], acc[7]);
    uint4 pk;
    pk.x = *reinterpret_cast<uint32_t*>(&h0);
    pk.y = *reinterpret_cast<uint32_t*>(&h1);
    pk.z = *reinterpret_cast<uint32_t*>(&h2);
    pk.w = *reinterpret_cast<uint32_t*>(&h3);
    *reinterpret_cast<uint4*>(outp + (size_t)p * 256 + lane * 8) = pk;
}

// ---------------- host ----------------
extern "C" void kernel_launch(void* const* d_in, const int* in_sizes, int n_in,
                              void* d_out, int out_size) {
    const float* x_q    = (const float*)d_in[0];
    const float* x_kv   = (const float*)d_in[1];
    const float* n1w    = (const float*)d_in[2];
    const float* n1b    = (const float*)d_in[3];
    const float* q_w    = (const float*)d_in[4];
    const float* q_b    = (const float*)d_in[5];
    const float* kv_w   = (const float*)d_in[6];
    const float* kv_b   = (const float*)d_in[7];
    const float* off1_w = (const float*)d_in[8];
    const float* off1_b = (const float*)d_in[9];
    const float* off2_w = (const float*)d_in[10];
    const float* off2_b = (const float*)d_in[11];
    const float* proj_w = (const float*)d_in[12];
    const float* proj_b = (const float*)d_in[13];
    const float* n2w    = (const float*)d_in[14];
    const float* n2b    = (const float*)d_in[15];
    const float* fc1_w  = (const float*)d_in[16];
    const float* fc1_b  = (const float*)d_in[17];
    const float* fc2_w  = (const float*)d_in[18];
    const float* fc2_b  = (const float*)d_in[19];
    float* out = (float*)d_out;

    __half *xall, *qb, *kvb, *h1, *att, *xn2, *hid, *wrw, *wh, *U, *V;
    float *offs, *xres, *st1, *st2, *zerob;
    float2* part;
    cudaGetSymbolAddress((void**)&xall, g_xall);
    cudaGetSymbolAddress((void**)&qb,   g_q);
    cudaGetSymbolAddress((void**)&kvb,  g_kv);
    cudaGetSymbolAddress((void**)&h1,   g_h1);
    cudaGetSymbolAddress((void**)&U,    g_U);
    cudaGetSymbolAddress((void**)&V,    g_V);
    cudaGetSymbolAddress((void**)&offs, g_offs);
    cudaGetSymbolAddress((void**)&att,  g_att);
    cudaGetSymbolAddress((void**)&xres, g_xres);
    cudaGetSymbolAddress((void**)&xn2,  g_xn2);
    cudaGetSymbolAddress((void**)&hid,  g_hid);
    cudaGetSymbolAddress((void**)&wrw,  g_wrw);
    cudaGetSymbolAddress((void**)&wh,   g_wh);
    cudaGetSymbolAddress((void**)&zerob,g_zero);
    cudaGetSymbolAddress((void**)&part, g_part);
    cudaGetSymbolAddress((void**)&st1,  g_st1);
    cudaGetSymbolAddress((void**)&st2,  g_st2);

    __half* qwh  = wh;
    __half* kvwh = qwh  + 65536;
    __half* pwh  = kvwh + 131072;
    __half* f1wh = pwh  + 65536;
    __half* f2wh = f1wh + 262144;

    cudaFuncSetAttribute(gemm_tc, cudaFuncAttributeMaxDynamicSharedMemorySize, SMEM_REQ);

    prep_k<<<3584, 256>>>(off1_w, wrw, q_w, qwh, kv_w, kvwh, proj_w, pwh,
                          fc1_w, f1wh, fc2_w, f2wh);
    gn_p1<<<256, 256>>>(x_q, x_kv, part);
    gn_p2<<<1, 256>>>(part, st1, 8);
    norm_pack_k<<<dim3(128, 8, 8), dim3(32, 8)>>>(x_q, x_kv, st1, n1w, n1b, xall);
    wino_in_k<<<4096, 256>>>(xall, U);

    GJob zero = {};
    // fused winograd-conv + kv + q  (1024 + 512 + 256 CTAs)
    {
        GJob jw  = {U,           wrw,  zerob, (float*)V,   nullptr, 256, 512, 512, 6, 1, 0.f};
        GJob jkv = {xall + 256,  kvwh, kv_b,  (float*)kvb, nullptr, 512, 256, 512, 6, 0, 0.f};
        GJob jq  = {xall,        qwh,  q_b,   (float*)qb,  nullptr, 256, 256, 512, 1, 0,
                    0.17677669529663689f};
        gemm_tc<<<1792, 256, SMEM_REQ>>>(jw, jkv, jq, 1024, 1536);
    }
    wino_out_k<<<2048, 256>>>(V, off1_b, h1);
    off2_k<<<(MTOT * 18) / 256, 256>>>(h1, off2_w, off2_b, offs);
    attn_k<<<2048, 256>>>(qb, kvb, offs, att);
    // xres = x_q + att @ proj_w^T + b
    {
        GJob jp = {att, pwh, proj_b, xres, x_q, 256, 256, 256, 4, 0, 0.f};
        gemm_tc<<<256, 256, SMEM_REQ>>>(jp, zero, zero, 256, 256);
    }
    gn_p1<<<128, 256>>>(xres, xres, part);
    gn_p2<<<1, 256>>>(part, st2, 4);
    norm2_k<<<(MTOT * 256) / 256, 256>>>(xres, st2, n2w, n2b, xn2);
    // hid = gelu(xn2 @ fc1_w^T + b) -> half
    {
        GJob jf1 = {xn2, f1wh, fc1_b, (float*)hid, nullptr, 1024, 256, 256, 3, 0, 0.f};
        gemm_tc<<<1024, 256, SMEM_REQ>>>(jf1, zero, zero, 1024, 1024);
    }
    // out(NCHW) = xres + hid @ fc2_w^T + b   (256 CTAs)
    {
        GJob jf2 = {hid, f2wh, fc2_b, out, xres, 256, 1024, 1024, 5, 0, 0.f};
        gemm_tc<<<256, 256, SMEM_REQ>>>(jf2, zero, zero, 256, 256);
    }
}

// round 14
// speedup vs baseline: 1.0977x; 1.0084x over previous
#include <cuda_runtime.h>
#include <cuda_fp16.h>
#include <math.h>
#include <stdint.h>

#define MTOT 16384

// ---------------- scratch ----------------
__device__ __align__(1024) __half g_xall[(size_t)MTOT * 512];
__device__ __align__(1024) __half g_q   [(size_t)MTOT * 256];
__device__ __align__(1024) __half g_kv  [(size_t)MTOT * 512];
__device__ __align__(1024) __half g_h1  [(size_t)MTOT * 256];
__device__ __align__(1024) __half g_U   [(size_t)65536 * 512];
__device__ __align__(1024) __half g_V   [(size_t)65536 * 256];
__device__ float  g_offs[(size_t)MTOT * 18];
__device__ __align__(1024) __half g_att [(size_t)MTOT * 256];
__device__ float  g_xres[(size_t)MTOT * 256];
__device__ __align__(1024) __half g_xn2 [(size_t)MTOT * 256];
__device__ __align__(1024) __half g_hid [(size_t)MTOT * 1024];
__device__ __align__(1024) __half g_wrw [16 * 256 * 512];
__device__ __align__(1024) __half g_wh  [65536 + 131072 + 65536 + 262144 + 262144];
__device__ float  g_zero[256];
__device__ float2 g_part[256];
__device__ float  g_st1 [16];
__device__ float  g_st2 [8];
__device__ unsigned g_cnt1 = 0;
__device__ unsigned g_cnt2 = 0;

// ---------------- fused front: weight prep (wino + 5x f2h) + gn1 stats ----------------
// blocks [0,3584): prep work (917504 elements). blocks [3584,3840): gn phase1+2.
__global__ void front_k(const float* __restrict__ off1_w, __half* __restrict__ wrw,
                        const float* __restrict__ q_w,    __half* __restrict__ qwh,
                        const float* __restrict__ kv_w,   __half* __restrict__ kvwh,
                        const float* __restrict__ proj_w, __half* __restrict__ pwh,
                        const float* __restrict__ fc1_w,  __half* __restrict__ f1wh,
                        const float* __restrict__ fc2_w,  __half* __restrict__ f2wh,
                        const float* __restrict__ x_q,    const float* __restrict__ x_kv,
                        float2* __restrict__ part, float* __restrict__ stats) {
    if (blockIdx.x < 3584) {
        int id = blockIdx.x * 256 + threadIdx.x;
        if (id < 131072) {
            int o = id >> 9, c = id & 511;
            const float* g = off1_w + (size_t)(o * 512 + c) * 9;
            float r[4][3];
#pragma unroll
            for (int j = 0; j < 3; j++) {
                float g0 = g[j], g1 = g[3 + j], g2 = g[6 + j];
                r[0][j] = g0;
                r[1][j] = 0.5f * (g0 + g1 + g2);
                r[2][j] = 0.5f * (g0 - g1 + g2);
                r[3][j] = g2;
            }
#pragma unroll
            for (int i = 0; i < 4; i++) {
                float w0 = r[i][0], w1 = 0.5f * (r[i][0] + r[i][1] + r[i][2]);
                float w2 = 0.5f * (r[i][0] - r[i][1] + r[i][2]), w3 = r[i][2];
                wrw[(((size_t)(i * 4 + 0) * 256 + o) << 9) + c] = __float2half(w0);
                wrw[(((size_t)(i * 4 + 1) * 256 + o) << 9) + c] = __float2half(w1);
                wrw[(((size_t)(i * 4 + 2) * 256 + o) << 9) + c] = __float2half(w2);
                wrw[(((size_t)(i * 4 + 3) * 256 + o) << 9) + c] = __float2half(w3);
            }
            return;
        }
        id -= 131072;
        if (id < 65536)  { qwh [id] = __float2half(q_w [id]); return; }  id -= 65536;
        if (id < 131072) { kvwh[id] = __float2half(kv_w[id]); return; }  id -= 131072;
        if (id < 65536)  { pwh [id] = __float2half(proj_w[id]); return; } id -= 65536;
        if (id < 262144) { f1wh[id] = __float2half(fc1_w[id]); return; }  id -= 262144;
        f2wh[id] = __float2half(fc2_w[id]);
        return;
    }
    // ---- gn phase 1 ----
    int bi = blockIdx.x - 3584;          // 0..255
    int slab = bi >> 5, chunk = bi & 31;
    int tensor = slab >> 2, batch = slab & 3;
    const float* src = (tensor ? x_kv : x_q) + ((size_t)batch << 20) + ((size_t)chunk << 15);
    const float4* p4 = reinterpret_cast<const float4*>(src);
    float s = 0.f, s2 = 0.f;
    for (int i = threadIdx.x; i < 8192; i += 256) {
        float4 v = p4[i];
        s  += v.x + v.y + v.z + v.w;
        s2 += v.x * v.x + v.y * v.y + v.z * v.z + v.w * v.w;
    }
    __shared__ float sh1[256], sh2[256];
    sh1[threadIdx.x] = s; sh2[threadIdx.x] = s2;
    __syncthreads();
    for (int st = 128; st > 0; st >>= 1) {
        if (threadIdx.x < st) { sh1[threadIdx.x] += sh1[threadIdx.x + st];
                                sh2[threadIdx.x] += sh2[threadIdx.x + st]; }
        __syncthreads();
    }
    __shared__ bool last;
    if (threadIdx.x == 0) {
        part[slab * 32 + chunk] = make_float2(sh1[0], sh2[0]);
        __threadfence();
        last = (atomicInc(&g_cnt1, 0xFFFFFFFFu) == 255);
    }
    __syncthreads();
    if (!last) return;
    // ---- gn phase 2 (last block; fixed-order reduction -> deterministic) ----
    int sl2 = threadIdx.x >> 5, lane = threadIdx.x & 31;
    float a = part[sl2 * 32 + lane].x, b = part[sl2 * 32 + lane].y;
#pragma unroll
    for (int off = 16; off > 0; off >>= 1) {
        a += __shfl_xor_sync(0xffffffffu, a, off);
        b += __shfl_xor_sync(0xffffffffu, b, off);
    }
    if (lane == 0) {
        float inv = 1.f / 1048576.f;
        float mu = a * inv;
        float var = b * inv - mu * mu;
        stats[sl2 * 2] = mu;
        stats[sl2 * 2 + 1] = rsqrtf(var + 1e-5f);
    }
    __syncthreads();
    if (threadIdx.x == 0) g_cnt1 = 0;    // reset for next graph replay
}

// ---------------- xres stats: phase1 + in-kernel phase2 ----------------
__global__ void gnx_k(const float* __restrict__ xres, float2* __restrict__ part,
                      float* __restrict__ stats) {
    int bi = blockIdx.x;                  // 0..127
    int slab = bi >> 5, chunk = bi & 31;  // slab = batch (4 slabs)
    const float* src = xres + ((size_t)slab << 20) + ((size_t)chunk << 15);
    const float4* p4 = reinterpret_cast<const float4*>(src);
    float s = 0.f, s2 = 0.f;
    for (int i = threadIdx.x; i < 8192; i += 256) {
        float4 v = p4[i];
        s  += v.x + v.y + v.z + v.w;
        s2 += v.x * v.x + v.y * v.y + v.z * v.z + v.w * v.w;
    }
    __shared__ float sh1[256], sh2[256];
    sh1[threadIdx.x] = s; sh2[threadIdx.x] = s2;
    __syncthreads();
    for (int st = 128; st > 0; st >>= 1) {
        if (threadIdx.x < st) { sh1[threadIdx.x] += sh1[threadIdx.x + st];
                                sh2[threadIdx.x] += sh2[threadIdx.x + st]; }
        __syncthreads();
    }
    __shared__ bool last;
    if (threadIdx.x == 0) {
        part[slab * 32 + chunk] = make_float2(sh1[0], sh2[0]);
        __threadfence();
        last = (atomicInc(&g_cnt2, 0xFFFFFFFFu) == 127);
    }
    __syncthreads();
    if (!last) return;
    int sl2 = threadIdx.x >> 5, lane = threadIdx.x & 31;
    if (sl2 < 4) {
        float a = part[sl2 * 32 + lane].x, b = part[sl2 * 32 + lane].y;
#pragma unroll
        for (int off = 16; off > 0; off >>= 1) {
            a += __shfl_xor_sync(0xffffffffu, a, off);
            b += __shfl_xor_sync(0xffffffffu, b, off);
        }
        if (lane == 0) {
            float inv = 1.f / 1048576.f;
            float mu = a * inv;
            float var = b * inv - mu * mu;
            stats[sl2 * 2] = mu;
            stats[sl2 * 2 + 1] = rsqrtf(var + 1e-5f);
        }
    }
    __syncthreads();
    if (threadIdx.x == 0) g_cnt2 = 0;
}

// ---------------- normalize + NCHW->NHWC pack (half2 stores, 64-ch tiles) ----------------
__global__ void norm_pack_k(const float* __restrict__ xq, const float* __restrict__ xkv,
                            const float* __restrict__ stats, const float* __restrict__ w,
                            const float* __restrict__ bb, __half* __restrict__ xall) {
    __shared__ float tile[64][33];
    int bz = blockIdx.z;
    int tensor = bz >> 2, batch = bz & 3;
    const float* src = (tensor == 0 ? xq : xkv) + ((size_t)batch << 20);
    float mu = stats[bz * 2], rstd = stats[bz * 2 + 1];
    int s0 = blockIdx.x * 32, c0 = blockIdx.y * 64;
    int tx = threadIdx.x, ty = threadIdx.y;
#pragma unroll
    for (int k = 0; k < 8; k++) {
        int c = c0 + ty + k * 8;
        tile[ty + k * 8][tx] = src[(size_t)c * 4096 + s0 + tx];
    }
    __syncthreads();
    int c = c0 + 2 * tx;
    float w0 = w[c], w1 = w[c + 1], bb0 = bb[c], bb1 = bb[c + 1];
#pragma unroll
    for (int k = 0; k < 4; k++) {
        int sl = ty + k * 8;
        float v0 = (tile[2 * tx][sl] - mu) * rstd * w0 + bb0;
        float v1 = (tile[2 * tx + 1][sl] - mu) * rstd * w1 + bb1;
        __half2 hv = __floats2half2_rn(v0, v1);
        *reinterpret_cast<uint32_t*>(
            xall + (((size_t)batch * 4096 + s0 + sl) << 9) + tensor * 256 + c) =
            *reinterpret_cast<uint32_t*>(&hv);
    }
}

// ---------------- winograd input transform ----------------
__global__ void wino_in_k(const __half* __restrict__ xall, __half* __restrict__ U) {
    int id = blockIdx.x * 256 + threadIdx.x;
    int c2 = id & 255, t = id >> 8;
    int c = c2 << 1;
    int b = t >> 10, sp = t & 1023, ty = sp >> 5, tx = sp & 31;
    int y0 = (ty << 1) - 1, x0 = (tx << 1) - 1;
    float d0[4][4], d1[4][4];
#pragma unroll
    for (int i = 0; i < 4; i++) {
        int yy = y0 + i;
#pragma unroll
        for (int j = 0; j < 4; j++) {
            int xx = x0 + j;
            if (yy >= 0 && yy < 64 && xx >= 0 && xx < 64) {
                uint32_t v = *reinterpret_cast<const uint32_t*>(
                    xall + (((size_t)(b << 12) + (yy << 6) + xx) << 9) + c);
                float2 f = __half22float2(*reinterpret_cast<__half2*>(&v));
                d0[i][j] = f.x; d1[i][j] = f.y;
            } else { d0[i][j] = 0.f; d1[i][j] = 0.f; }
        }
    }
    float t0[4][4], t1[4][4];
#pragma unroll
    for (int j = 0; j < 4; j++) {
        t0[0][j] = d0[0][j] - d0[2][j]; t1[0][j] = d1[0][j] - d1[2][j];
        t0[1][j] = d0[1][j] + d0[2][j]; t1[1][j] = d1[1][j] + d1[2][j];
        t0[2][j] = d0[2][j] - d0[1][j]; t1[2][j] = d1[2][j] - d1[1][j];
        t0[3][j] = d0[1][j] - d0[3][j]; t1[3][j] = d1[1][j] - d1[3][j];
    }
#pragma unroll
    for (int i = 0; i < 4; i++) {
        float u0[4], u1[4];
        u0[0] = t0[i][0] - t0[i][2]; u1[0] = t1[i][0] - t1[i][2];
        u0[1] = t0[i][1] + t0[i][2]; u1[1] = t1[i][1] + t1[i][2];
        u0[2] = t0[i][2] - t0[i][1]; u1[2] = t1[i][2] - t1[i][1];
        u0[3] = t0[i][1] - t0[i][3]; u1[3] = t1[i][1] - t1[i][3];
#pragma unroll
        for (int j = 0; j < 4; j++) {
            __half2 hv = __floats2half2_rn(u0[j], u1[j]);
            *reinterpret_cast<uint32_t*>(
                U + (((size_t)(i * 4 + j) * 4096 + t) << 9) + c) =
                *reinterpret_cast<uint32_t*>(&hv);
        }
    }
}

// ---------------- winograd output transform (bias + relu) ----------------
__global__ void wino_out_k(const __half* __restrict__ V, const float* __restrict__ bias,
                           __half* __restrict__ h1) {
    int id = blockIdx.x * 256 + threadIdx.x;
    int o2 = id & 127, t = id >> 7;
    int o = o2 << 1;
    int b = t >> 10, sp = t & 1023, ty = sp >> 5, tx = sp & 31;
    float m0[4][4], m1[4][4];
#pragma unroll
    for (int i = 0; i < 4; i++)
#pragma unroll
        for (int j = 0; j < 4; j++) {
            uint32_t v = *reinterpret_cast<const uint32_t*>(
                V + (((size_t)(i * 4 + j) * 4096 + t) << 8) + o);
            float2 f = __half22float2(*reinterpret_cast<__half2*>(&v));
            m0[i][j] = f.x; m1[i][j] = f.y;
        }
    float b0 = bias[o], b1 = bias[o + 1];
    float p00[4], p01[4], p10[4], p11[4];
#pragma unroll
    for (int j = 0; j < 4; j++) {
        p00[j] = m0[0][j] + m0[1][j] + m0[2][j];
        p01[j] = m0[1][j] - m0[2][j] - m0[3][j];
        p10[j] = m1[0][j] + m1[1][j] + m1[2][j];
        p11[j] = m1[1][j] - m1[2][j] - m1[3][j];
    }
    float y0[2][2], y1[2][2];
    y0[0][0] = p00[0] + p00[1] + p00[2];  y0[0][1] = p00[1] - p00[2] - p00[3];
    y0[1][0] = p01[0] + p01[1] + p01[2];  y0[1][1] = p01[1] - p01[2] - p01[3];
    y1[0][0] = p10[0] + p10[1] + p10[2];  y1[0][1] = p10[1] - p10[2] - p10[3];
    y1[1][0] = p11[0] + p11[1] + p11[2];  y1[1][1] = p11[1] - p11[2] - p11[3];
#pragma unroll
    for (int r = 0; r < 2; r++)
#pragma unroll
        for (int cc = 0; cc < 2; cc++) {
            float v0 = fmaxf(y0[r][cc] + b0, 0.f);
            float v1 = fmaxf(y1[r][cc] + b1, 0.f);
            __half2 hv = __floats2half2_rn(v0, v1);
            int py = (ty << 1) + r, px = (tx << 1) + cc;
            *reinterpret_cast<uint32_t*>(
                h1 + (((size_t)(b << 12) + (py << 6) + px) << 8) + o) =
                *reinterpret_cast<uint32_t*>(&hv);
        }
}

// ---------------- norm2 (fp16 out) ----------------
__global__ void norm2_k(const float* __restrict__ xres, const float* __restrict__ stats,
                        const float* __restrict__ w, const float* __restrict__ bb,
                        __half* __restrict__ xn) {
    int id = blockIdx.x * blockDim.x + threadIdx.x;
    if (id >= MTOT * 256) return;
    int b = id >> 20, c = id & 255;
    xn[id] = __float2half((xres[id] - stats[b * 2]) * stats[b * 2 + 1] * w[c] + bb[c]);
}

// ---------------- PTX helpers ----------------
__device__ __forceinline__ void mma16(float4& d, const uint32_t* a, const uint32_t* b) {
    asm volatile("mma.sync.aligned.m16n8k16.row.col.f32.f16.f16.f32 "
        "{%0,%1,%2,%3}, {%4,%5,%6,%7}, {%8,%9}, {%0,%1,%2,%3};\n"
        : "+f"(d.x), "+f"(d.y), "+f"(d.z), "+f"(d.w)
        : "r"(a[0]), "r"(a[1]), "r"(a[2]), "r"(a[3]), "r"(b[0]), "r"(b[1]));
}
__device__ __forceinline__ void ldsm4(uint32_t* r, uint32_t a) {
    asm volatile("ldmatrix.sync.aligned.m8n8.x4.shared.b16 {%0,%1,%2,%3}, [%4];"
        : "=r"(r[0]), "=r"(r[1]), "=r"(r[2]), "=r"(r[3]) : "r"(a));
}
__device__ __forceinline__ void cp16(uint32_t d, const void* s, int sz) {
    asm volatile("cp.async.cg.shared.global [%0], [%1], 16, %2;"
        :: "r"(d), "l"(s), "r"(sz));
}
#define CP_COMMIT() asm volatile("cp.async.commit_group;")

// ---------------- multi-job fp16 tensor-core GEMM ----------------
#define STG_BYTES 32768
#define SMEM_REQ  (3 * STG_BYTES)

struct GJob {
    const __half* A; const __half* W; const float* bias; float* C; const float* R;
    int N, K, lda, mode, wino; float scale;
};

__device__ __forceinline__ void issue_tile(
    uint32_t sa0, const __half* __restrict__ A, const __half* __restrict__ W,
    int bm, int bn, int K0, int lda, int K, int lrow, int g)
{
    uint32_t sa = sa0 + lrow * 128;
    const __half* srcA = A + (size_t)(bm + lrow) * lda + K0;
    const __half* srcB = W + (size_t)(bn + lrow) * (size_t)K + K0;
    const int r7 = lrow & 7;
#pragma unroll
    for (int j = 0; j < 4; j++) {
        const int c = g + j;
        const uint32_t off = (uint32_t)((c ^ r7) << 4);
        cp16(sa + off, srcA + c * 8, 16);
        cp16(sa + 16384 + off, srcB + c * 8, 16);
    }
}

__global__ void __launch_bounds__(256, 2) gemm_tc(
    GJob j0, GJob j1, GJob j2, int c0, int c1)
{
    extern __shared__ float smbuf[];
    const uint32_t smem_base = (uint32_t)__cvta_generic_to_shared(smbuf);

    GJob J;
    int local;
    {
        const int id = blockIdx.x;
        if (id < c0)      { J = j0; local = id; }
        else if (id < c1) { J = j1; local = id - c0; }
        else              { J = j2; local = id - c1; }
    }
    const int bnb = J.N >> 7;
    const int bm = (local / bnb) << 7, bn = (local % bnb) << 7;
    if (J.wino) J.W += ((size_t)(bm >> 12)) << 17;

    const int tid  = threadIdx.x;
    const int warp = tid >> 5, lane = tid & 31;
    const int wm   = (warp >> 2) << 6, wn = (warp & 3) << 5;
    const int lg   = lane >> 2, la3 = lane & 3;

    const int lrow = tid >> 1, g = (tid & 1) * 4;

    const int l7 = lane & 7, lq = lane >> 3;
    uint32_t arow[4], brow[2];
#pragma unroll
    for (int mt = 0; mt < 4; mt++)
        arow[mt] = (uint32_t)((wm + mt * 16 + ((lq & 1) << 3) + l7) * 128);
    const int a_kq = lq >> 1;
#pragma unroll
    for (int p = 0; p < 2; p++)
        brow[p] = (uint32_t)(16384 + (wn + p * 16 + ((lq >> 1) << 3) + l7) * 128);
    const int b_kq = lq & 1;

    float4 acc[4][4];
#pragma unroll
    for (int i = 0; i < 4; i++)
#pragma unroll
        for (int j = 0; j < 4; j++) acc[i][j] = make_float4(0.f, 0.f, 0.f, 0.f);

    const int nkb = J.K >> 6;
    issue_tile(smem_base,             J.A, J.W, bm, bn,  0, J.lda, J.K, lrow, g);
    CP_COMMIT();
    issue_tile(smem_base + STG_BYTES, J.A, J.W, bm, bn, 64, J.lda, J.K, lrow, g);
    CP_COMMIT();

    int stg = 0;
    for (int kb = 0; kb < nkb; kb++) {
        asm volatile("cp.async.wait_group 1;");
        __syncthreads();
        if (kb + 2 < nkb) {
            int s2 = stg + 2; if (s2 >= 3) s2 -= 3;
            issue_tile(smem_base + s2 * STG_BYTES, J.A, J.W, bm, bn,
                       (kb + 2) << 6, J.lda, J.K, lrow, g);
        }
        CP_COMMIT();

        const uint32_t Ab = smem_base + stg * STG_BYTES;
#pragma unroll
        for (int ks = 0; ks < 4; ks++) {
            const uint32_t axor = (uint32_t)((((ks << 1) + a_kq) ^ l7) << 4);
            const uint32_t bxor = (uint32_t)((((ks << 1) + b_kq) ^ l7) << 4);
            uint32_t af[4][4], bf[2][4];
#pragma unroll
            for (int mt = 0; mt < 4; mt++) ldsm4(af[mt], Ab + arow[mt] + axor);
#pragma unroll
            for (int p = 0; p < 2; p++)    ldsm4(bf[p],  Ab + brow[p] + bxor);
#pragma unroll
            for (int mt = 0; mt < 4; mt++) {
                mma16(acc[mt][0], af[mt], &bf[0][0]);
                mma16(acc[mt][1], af[mt], &bf[0][2]);
                mma16(acc[mt][2], af[mt], &bf[1][0]);
                mma16(acc[mt][3], af[mt], &bf[1][2]);
            }
        }
        if (++stg == 3) stg = 0;
    }

    // ---------------- epilogue ----------------
    const bool halfout = (J.mode == 1) || (J.mode == 2) || (J.mode == 3) || (J.mode == 6);
#pragma unroll
    for (int mt = 0; mt < 4; mt++) {
        const int m0 = bm + wm + (mt << 4) + lg;
#pragma unroll
        for (int nt = 0; nt < 4; nt++) {
            const int n = bn + wn + (nt << 3) + (la3 << 1);
            const float b0 = J.bias[n], b1 = J.bias[n + 1];
            float v[4] = {acc[mt][nt].x + b0, acc[mt][nt].y + b1,
                          acc[mt][nt].z + b0, acc[mt][nt].w + b1};
#pragma unroll
            for (int h = 0; h < 2; h++) {
                const int m = m0 + h * 8;
                if (halfout) {
                    float x0 = v[h * 2], x1 = v[h * 2 + 1];
                    if (J.mode == 1) { x0 *= J.scale; x1 *= J.scale; }
                    else if (J.mode == 2) { x0 = fmaxf(x0, 0.f); x1 = fmaxf(x1, 0.f); }
                    else if (J.mode == 3) {
                        x0 = 0.5f * x0 * (1.f + erff(x0 * 0.70710678118654752f));
                        x1 = 0.5f * x1 * (1.f + erff(x1 * 0.70710678118654752f));
                    }
                    *reinterpret_cast<__half2*>(
                        reinterpret_cast<__half*>(J.C) + (size_t)m * (size_t)J.N + n) =
                        __floats2half2_rn(x0, x1);
                } else {
#pragma unroll
                    for (int j = 0; j < 2; j++) {
                        float x = v[h * 2 + j];
                        const int nn = n + j;
                        if (J.mode == 4) x += J.R[((size_t)(m >> 12) * 256 + nn) * 4096 + (m & 4095)];
                        else if (J.mode == 5) x += J.R[(size_t)m * 256 + nn];
                        if (J.mode == 5)
                            J.C[((size_t)(m >> 12) * 256 + nn) * 4096 + (m & 4095)] = x;
                        else
                            J.C[(size_t)m * (size_t)J.N + nn] = x;
                    }
                }
            }
        }
    }
}

// ---------------- offset head (fp16 h1) ----------------
__global__ void off2_k(const __half* __restrict__ h1, const float* __restrict__ w,
                       const float* __restrict__ bias, float* __restrict__ offs) {
    int id = blockIdx.x * blockDim.x + threadIdx.x;
    if (id >= MTOT * 18) return;
    int m = id / 18, n = id - m * 18;
    const uint4* a = reinterpret_cast<const uint4*>(h1 + (size_t)m * 256);
    const float4* ww = reinterpret_cast<const float4*>(w + (size_t)n * 256);
    float s = bias[n];
#pragma unroll 8
    for (int k = 0; k < 32; k++) {
        uint4 av = a[k];
        const __half2* hh = reinterpret_cast<const __half2*>(&av);
        float2 f0 = __half22float2(hh[0]), f1 = __half22float2(hh[1]);
        float2 f2 = __half22float2(hh[2]), f3 = __half22float2(hh[3]);
        float4 w0 = ww[2 * k], w1 = ww[2 * k + 1];
        s += f0.x * w0.x + f0.y * w0.y + f1.x * w0.z + f1.y * w0.w;
        s += f2.x * w1.x + f2.y * w1.y + f3.x * w1.z + f3.y * w1.w;
    }
    offs[id] = s;
}

// ---------------- fused bilinear-sample + 9-way attention (fp16) ----------------
#define LOAD8H(dst, ptr)                                                    \
    {                                                                       \
        uint4 _u = *reinterpret_cast<const uint4*>(ptr);                    \
        __half2* _hh = reinterpret_cast<__half2*>(&_u);                     \
        float2 _f0 = __half22float2(_hh[0]), _f1 = __half22float2(_hh[1]);  \
        float2 _f2 = __half22float2(_hh[2]), _f3 = __half22float2(_hh[3]);  \
        dst[0] = _f0.x; dst[1] = _f0.y; dst[2] = _f1.x; dst[3] = _f1.y;     \
        dst[4] = _f2.x; dst[5] = _f2.y; dst[6] = _f3.x; dst[7] = _f3.y;     \
    }

__global__ void __launch_bounds__(256) attn_k(
    const __half* __restrict__ qb, const __half* __restrict__ kv,
    const float* __restrict__ offs, __half* __restrict__ outp) {
    __shared__ float sh[8][9][8];
    const int warp = threadIdx.x >> 5, lane = threadIdx.x & 31;
    const int p = blockIdx.x * 8 + warp;
    const int b = p >> 12, s = p & 4095, y = s >> 6, x = s & 63;
    const __half* kvb = kv + (((size_t)b << 12) << 9);

    float qr[8];
    LOAD8H(qr, qb + (size_t)p * 256 + lane * 8);

    for (int o = 0; o < 9; o++) {
        int ys = y + o / 3 - 1, xs = x + o % 3 - 1;
        float prod[8] = {0.f, 0.f, 0.f, 0.f, 0.f, 0.f, 0.f, 0.f};
        if (ys >= 0 && ys < 64 && xs >= 0 && xs < 64) {
            const float* op = offs + (size_t)((b << 12) + (ys << 6) + xs) * 18 + 2 * o;
            float px = op[0], py = op[1];
            float y0f = floorf(py), x0f = floorf(px);
            float wy = py - y0f, wx = px - x0f;
            int y0 = (int)y0f, x0 = (int)x0f;
            float w00 = (1.f - wy) * (1.f - wx), w01 = (1.f - wy) * wx;
            float w10 = wy * (1.f - wx), w11 = wy * wx;
            bool vy0 = (y0 >= 0) && (y0 < 64), vy1 = (y0 + 1 >= 0) && (y0 + 1 < 64);
            bool vx0 = (x0 >= 0) && (x0 < 64), vx1 = (x0 + 1 >= 0) && (x0 + 1 < 64);
            w00 = (vy0 && vx0) ? w00 : 0.f; w01 = (vy0 && vx1) ? w01 : 0.f;
            w10 = (vy1 && vx0) ? w10 : 0.f; w11 = (vy1 && vx1) ? w11 : 0.f;
            int y0c = min(max(y0, 0), 63), y1c = min(max(y0 + 1, 0), 63);
            int x0c = min(max(x0, 0), 63), x1c = min(max(x0 + 1, 0), 63);
            float c00[8], c01[8], c10[8], c11[8];
            LOAD8H(c00, kvb + ((size_t)((y0c << 6) + x0c) << 9) + lane * 8);
            LOAD8H(c01, kvb + ((size_t)((y0c << 6) + x1c) << 9) + lane * 8);
            LOAD8H(c10, kvb + ((size_t)((y1c << 6) + x0c) << 9) + lane * 8);
            LOAD8H(c11, kvb + ((size_t)((y1c << 6) + x1c) << 9) + lane * 8);
#pragma unroll
            for (int h = 0; h < 8; h++) {
                float kvv = w00 * c00[h] + w01 * c01[h] + w10 * c10[h] + w11 * c11[h];
                prod[h] = qr[h] * kvv;
            }
        }
#pragma unroll
        for (int off = 16; off > 0; off >>= 1)
#pragma unroll
            for (int h = 0; h < 8; h++)
                prod[h] += __shfl_xor_sync(0xffffffffu, prod[h], off);
        if (lane == 0) {
#pragma unroll
            for (int h = 0; h < 8; h++) sh[warp][o][h] = prod[h];
        }
    }
    __syncwarp();
    if (lane < 8) {
        float e[9]; float mx = -1e30f;
#pragma unroll
        for (int o = 0; o < 9; o++) { e[o] = sh[warp][o][lane]; mx = fmaxf(mx, e[o]); }
        float sm = 0.f;
#pragma unroll
        for (int o = 0; o < 9; o++) { e[o] = expf(e[o] - mx); sm += e[o]; }
        float inv = 1.f / sm;
#pragma unroll
        for (int o = 0; o < 9; o++) sh[warp][o][lane] = e[o] * inv;
    }
    __syncwarp();
    float acc[8] = {0.f, 0.f, 0.f, 0.f, 0.f, 0.f, 0.f, 0.f};
    for (int o = 0; o < 9; o++) {
        int ys = y + o / 3 - 1, xs = x + o % 3 - 1;
        if (ys < 0 || ys >= 64 || xs < 0 || xs >= 64) continue;
        const float* op = offs + (size_t)((b << 12) + (ys << 6) + xs) * 18 + 2 * o;
        float px = op[0], py = op[1];
        float y0f = floorf(py), x0f = floorf(px);
        float wy = py - y0f, wx = px - x0f;
        int y0 = (int)y0f, x0 = (int)x0f;
        float w00 = (1.f - wy) * (1.f - wx), w01 = (1.f - wy) * wx;
        float w10 = wy * (1.f - wx), w11 = wy * wx;
        bool vy0 = (y0 >= 0) && (y0 < 64), vy1 = (y0 + 1 >= 0) && (y0 + 1 < 64);
        bool vx0 = (x0 >= 0) && (x0 < 64), vx1 = (x0 + 1 >= 0) && (x0 + 1 < 64);
        w00 = (vy0 && vx0) ? w00 : 0.f; w01 = (vy0 && vx1) ? w01 : 0.f;
        w10 = (vy1 && vx0) ? w10 : 0.f; w11 = (vy1 && vx1) ? w11 : 0.f;
        int y0c = min(max(y0, 0), 63), y1c = min(max(y0 + 1, 0), 63);
        int x0c = min(max(x0, 0), 63), x1c = min(max(x0 + 1, 0), 63);
        float c00[8], c01[8], c10[8], c11[8];
        LOAD8H(c00, kvb + ((size_t)((y0c << 6) + x0c) << 9) + 256 + lane * 8);
        LOAD8H(c01, kvb + ((size_t)((y0c << 6) + x1c) << 9) + 256 + lane * 8);
        LOAD8H(c10, kvb + ((size_t)((y1c << 6) + x0c) << 9) + 256 + lane * 8);
        LOAD8H(c11, kvb + ((size_t)((y1c << 6) + x1c) << 9) + 256 + lane * 8);
#pragma unroll
        for (int h = 0; h < 8; h++) {
            float vv = w00 * c00[h] + w01 * c01[h] + w10 * c10[h] + w11 * c11[h];
            acc[h] += sh[warp][o][h] * vv;
        }
    }
    __half2 h0 = __floats2half2_rn(acc[0], acc[1]);
    __half2 h1 = __floats2half2_rn(acc[2], acc[3]);
    __half2 h2 = __floats2half2_rn(acc[4], acc[5]);
    __half2 h3 = __floats2half2_rn(acc[6], acc[7]);
    uint4 pk;
    pk.x = *reinterpret_cast<uint32_t*>(&h0);
    pk.y = *reinterpret_cast<uint32_t*>(&h1);
    pk.z = *reinterpret_cast<uint32_t*>(&h2);
    pk.w = *reinterpret_cast<uint32_t*>(&h3);
    *reinterpret_cast<uint4*>(outp + (size_t)p * 256 + lane * 8) = pk;
}

// ---------------- host ----------------
extern "C" void kernel_launch(void* const* d_in, const int* in_sizes, int n_in,
                              void* d_out, int out_size) {
    const float* x_q    = (const float*)d_in[0];
    const float* x_kv   = (const float*)d_in[1];
    const float* n1w    = (const float*)d_in[2];
    const float* n1b    = (const float*)d_in[3];
    const float* q_w    = (const float*)d_in[4];
    const float* q_b    = (const float*)d_in[5];
    const float* kv_w   = (const float*)d_in[6];
    const float* kv_b   = (const float*)d_in[7];
    const float* off1_w = (const float*)d_in[8];
    const float* off1_b = (const float*)d_in[9];
    const float* off2_w = (const float*)d_in[10];
    const float* off2_b = (const float*)d_in[11];
    const float* proj_w = (const float*)d_in[12];
    const float* proj_b = (const float*)d_in[13];
    const float* n2w    = (const float*)d_in[14];
    const float* n2b    = (const float*)d_in[15];
    const float* fc1_w  = (const float*)d_in[16];
    const float* fc1_b  = (const float*)d_in[17];
    const float* fc2_w  = (const float*)d_in[18];
    const float* fc2_b  = (const float*)d_in[19];
    float* out = (float*)d_out;

    __half *xall, *qb, *kvb, *h1, *att, *xn2, *hid, *wrw, *wh, *U, *V;
    float *offs, *xres, *st1, *st2, *zerob;
    float2* part;
    cudaGetSymbolAddress((void**)&xall, g_xall);
    cudaGetSymbolAddress((void**)&qb,   g_q);
    cudaGetSymbolAddress((void**)&kvb,  g_kv);
    cudaGetSymbolAddress((void**)&h1,   g_h1);
    cudaGetSymbolAddress((void**)&U,    g_U);
    cudaGetSymbolAddress((void**)&V,    g_V);
    cudaGetSymbolAddress((void**)&offs, g_offs);
    cudaGetSymbolAddress((void**)&att,  g_att);
    cudaGetSymbolAddress((void**)&xres, g_xres);
    cudaGetSymbolAddress((void**)&xn2,  g_xn2);
    cudaGetSymbolAddress((void**)&hid,  g_hid);
    cudaGetSymbolAddress((void**)&wrw,  g_wrw);
    cudaGetSymbolAddress((void**)&wh,   g_wh);
    cudaGetSymbolAddress((void**)&zerob,g_zero);
    cudaGetSymbolAddress((void**)&part, g_part);
    cudaGetSymbolAddress((void**)&st1,  g_st1);
    cudaGetSymbolAddress((void**)&st2,  g_st2);

    __half* qwh  = wh;
    __half* kvwh = qwh  + 65536;
    __half* pwh  = kvwh + 131072;
    __half* f1wh = pwh  + 65536;
    __half* f2wh = f1wh + 262144;

    cudaFuncSetAttribute(gemm_tc, cudaFuncAttributeMaxDynamicSharedMemorySize, SMEM_REQ);

    // fused: weight prep + gn1 stats (phase1 + in-kernel phase2)
    front_k<<<3840, 256>>>(off1_w, wrw, q_w, qwh, kv_w, kvwh, proj_w, pwh,
                           fc1_w, f1wh, fc2_w, f2wh, x_q, x_kv, part, st1);
    norm_pack_k<<<dim3(128, 4, 8), dim3(32, 8)>>>(x_q, x_kv, st1, n1w, n1b, xall);
    wino_in_k<<<4096, 256>>>(xall, U);

    GJob zero = {};
    // fused winograd-conv + kv + q
    {
        GJob jw  = {U,           wrw,  zerob, (float*)V,   nullptr, 256, 512, 512, 6, 1, 0.f};
        GJob jkv = {xall + 256,  kvwh, kv_b,  (float*)kvb, nullptr, 512, 256, 512, 6, 0, 0.f};
        GJob jq  = {xall,        qwh,  q_b,   (float*)qb,  nullptr, 256, 256, 512, 1, 0,
                    0.17677669529663689f};
        gemm_tc<<<1792, 256, SMEM_REQ>>>(jw, jkv, jq, 1024, 1536);
    }
    wino_out_k<<<2048, 256>>>(V, off1_b, h1);
    off2_k<<<(MTOT * 18) / 256, 256>>>(h1, off2_w, off2_b, offs);
    attn_k<<<2048, 256>>>(qb, kvb, offs, att);
    // xres = x_q + att @ proj_w^T + b
    {
        GJob jp = {att, pwh, proj_b, xres, x_q, 256, 256, 256, 4, 0, 0.f};
        gemm_tc<<<256, 256, SMEM_REQ>>>(jp, zero, zero, 256, 256);
    }
    gnx_k<<<128, 256>>>(xres, part, st2);
    norm2_k<<<(MTOT * 256) / 256, 256>>>(xres, st2, n2w, n2b, xn2);
    // hid = gelu(xn2 @ fc1_w^T + b) -> half
    {
        GJob jf1 = {xn2, f1wh, fc1_b, (float*)hid, nullptr, 1024, 256, 256, 3, 0, 0.f};
        gemm_tc<<<1024, 256, SMEM_REQ>>>(jf1, zero, zero, 1024, 1024);
    }
    // out(NCHW) = xres + hid @ fc2_w^T + b   (256 CTAs)
    {
        GJob jf2 = {hid, f2wh, fc2_b, out, xres, 256, 1024, 1024, 5, 0, 0.f};
        gemm_tc<<<256, 256, SMEM_REQ>>>(jf2, zero, zero, 256, 256);
    }
}

// round 15
// speedup vs baseline: 1.1145x; 1.0153x over previous
#include <cuda_runtime.h>
#include <cuda_fp16.h>
#include <math.h>
#include <stdint.h>

#define MTOT 16384

// ---------------- scratch ----------------
__device__ __align__(1024) __half g_xall[(size_t)MTOT * 512];
__device__ __align__(1024) __half g_q   [(size_t)MTOT * 256];
__device__ __align__(1024) __half g_kv  [(size_t)MTOT * 512];
__device__ __align__(1024) __half g_h1  [(size_t)MTOT * 256];
__device__ __align__(1024) __half g_U   [(size_t)65536 * 512];
__device__ __align__(1024) __half g_V   [(size_t)65536 * 256];
__device__ float  g_offs[(size_t)MTOT * 18];
__device__ __align__(1024) __half g_att [(size_t)MTOT * 256];
__device__ float  g_xres[(size_t)MTOT * 256];
__device__ __align__(1024) __half g_xn2 [(size_t)MTOT * 256];
__device__ __align__(1024) __half g_hid [(size_t)MTOT * 1024];
__device__ __align__(1024) __half g_wrw [16 * 256 * 512];
__device__ __align__(1024) __half g_wh  [65536 + 131072 + 65536 + 262144 + 262144];
__device__ float  g_zero[256];
__device__ float2 g_part[256];
__device__ float  g_st1 [16];
__device__ float  g_st2 [8];
__device__ unsigned g_cnt1 = 0;
__device__ unsigned g_cnt2 = 0;
__device__ unsigned g_cnt3 = 0;
__device__ volatile int g_flag = 0;

// ---------------- fused front: weight prep (wino + 5x f2h) + gn1 stats ----------------
__global__ void front_k(const float* __restrict__ off1_w, __half* __restrict__ wrw,
                        const float* __restrict__ q_w,    __half* __restrict__ qwh,
                        const float* __restrict__ kv_w,   __half* __restrict__ kvwh,
                        const float* __restrict__ proj_w, __half* __restrict__ pwh,
                        const float* __restrict__ fc1_w,  __half* __restrict__ f1wh,
                        const float* __restrict__ fc2_w,  __half* __restrict__ f2wh,
                        const float* __restrict__ x_q,    const float* __restrict__ x_kv,
                        float2* __restrict__ part, float* __restrict__ stats) {
    if (blockIdx.x < 3584) {
        int id = blockIdx.x * 256 + threadIdx.x;
        if (id < 131072) {
            int o = id >> 9, c = id & 511;
            const float* g = off1_w + (size_t)(o * 512 + c) * 9;
            float r[4][3];
#pragma unroll
            for (int j = 0; j < 3; j++) {
                float g0 = g[j], g1 = g[3 + j], g2 = g[6 + j];
                r[0][j] = g0;
                r[1][j] = 0.5f * (g0 + g1 + g2);
                r[2][j] = 0.5f * (g0 - g1 + g2);
                r[3][j] = g2;
            }
#pragma unroll
            for (int i = 0; i < 4; i++) {
                float w0 = r[i][0], w1 = 0.5f * (r[i][0] + r[i][1] + r[i][2]);
                float w2 = 0.5f * (r[i][0] - r[i][1] + r[i][2]), w3 = r[i][2];
                wrw[(((size_t)(i * 4 + 0) * 256 + o) << 9) + c] = __float2half(w0);
                wrw[(((size_t)(i * 4 + 1) * 256 + o) << 9) + c] = __float2half(w1);
                wrw[(((size_t)(i * 4 + 2) * 256 + o) << 9) + c] = __float2half(w2);
                wrw[(((size_t)(i * 4 + 3) * 256 + o) << 9) + c] = __float2half(w3);
            }
            return;
        }
        id -= 131072;
        if (id < 65536)  { qwh [id] = __float2half(q_w [id]); return; }  id -= 65536;
        if (id < 131072) { kvwh[id] = __float2half(kv_w[id]); return; }  id -= 131072;
        if (id < 65536)  { pwh [id] = __float2half(proj_w[id]); return; } id -= 65536;
        if (id < 262144) { f1wh[id] = __float2half(fc1_w[id]); return; }  id -= 262144;
        f2wh[id] = __float2half(fc2_w[id]);
        return;
    }
    int bi = blockIdx.x - 3584;
    int slab = bi >> 5, chunk = bi & 31;
    int tensor = slab >> 2, batch = slab & 3;
    const float* src = (tensor ? x_kv : x_q) + ((size_t)batch << 20) + ((size_t)chunk << 15);
    const float4* p4 = reinterpret_cast<const float4*>(src);
    float s = 0.f, s2 = 0.f;
    for (int i = threadIdx.x; i < 8192; i += 256) {
        float4 v = p4[i];
        s  += v.x + v.y + v.z + v.w;
        s2 += v.x * v.x + v.y * v.y + v.z * v.z + v.w * v.w;
    }
    __shared__ float sh1[256], sh2[256];
    sh1[threadIdx.x] = s; sh2[threadIdx.x] = s2;
    __syncthreads();
    for (int st = 128; st > 0; st >>= 1) {
        if (threadIdx.x < st) { sh1[threadIdx.x] += sh1[threadIdx.x + st];
                                sh2[threadIdx.x] += sh2[threadIdx.x + st]; }
        __syncthreads();
    }
    __shared__ bool last;
    if (threadIdx.x == 0) {
        part[slab * 32 + chunk] = make_float2(sh1[0], sh2[0]);
        __threadfence();
        last = (atomicInc(&g_cnt1, 0xFFFFFFFFu) == 255);
    }
    __syncthreads();
    if (!last) return;
    int sl2 = threadIdx.x >> 5, lane = threadIdx.x & 31;
    float a = part[sl2 * 32 + lane].x, b = part[sl2 * 32 + lane].y;
#pragma unroll
    for (int off = 16; off > 0; off >>= 1) {
        a += __shfl_xor_sync(0xffffffffu, a, off);
        b += __shfl_xor_sync(0xffffffffu, b, off);
    }
    if (lane == 0) {
        float inv = 1.f / 1048576.f;
        float mu = a * inv;
        float var = b * inv - mu * mu;
        stats[sl2 * 2] = mu;
        stats[sl2 * 2 + 1] = rsqrtf(var + 1e-5f);
    }
    __syncthreads();
    if (threadIdx.x == 0) g_cnt1 = 0;
}

// ---------------- fused xres stats + norm2: 128 co-resident blocks, spin on flag ----------------
__global__ void __launch_bounds__(256) gnxn_k(
    const float* __restrict__ xres, float2* __restrict__ part, float* __restrict__ stats,
    const float* __restrict__ w, const float* __restrict__ bb, __half* __restrict__ xn) {
    int bi = blockIdx.x;                  // 0..127
    int slab = bi >> 5, chunk = bi & 31;  // slab = batch
    const size_t base4 = ((size_t)slab << 18) + ((size_t)chunk << 13);   // float4 units
    const float4* p4 = reinterpret_cast<const float4*>(xres) + base4;
    float s = 0.f, s2 = 0.f;
    float4 cache[32];
#pragma unroll
    for (int i = 0; i < 32; i++) {
        float4 v = p4[threadIdx.x + (i << 8)];
        cache[i] = v;
        s  += v.x + v.y + v.z + v.w;
        s2 += v.x * v.x + v.y * v.y + v.z * v.z + v.w * v.w;
    }
    __shared__ float sh1[256], sh2[256];
    sh1[threadIdx.x] = s; sh2[threadIdx.x] = s2;
    __syncthreads();
    for (int st = 128; st > 0; st >>= 1) {
        if (threadIdx.x < st) { sh1[threadIdx.x] += sh1[threadIdx.x + st];
                                sh2[threadIdx.x] += sh2[threadIdx.x + st]; }
        __syncthreads();
    }
    __shared__ bool last;
    if (threadIdx.x == 0) {
        part[slab * 32 + chunk] = make_float2(sh1[0], sh2[0]);
        __threadfence();
        last = (atomicInc(&g_cnt2, 0xFFFFFFFFu) == 127);
    }
    __syncthreads();
    if (last) {
        int sl2 = threadIdx.x >> 5, lane = threadIdx.x & 31;
        if (sl2 < 4) {
            float a = part[sl2 * 32 + lane].x, b = part[sl2 * 32 + lane].y;
#pragma unroll
            for (int off = 16; off > 0; off >>= 1) {
                a += __shfl_xor_sync(0xffffffffu, a, off);
                b += __shfl_xor_sync(0xffffffffu, b, off);
            }
            if (lane == 0) {
                float inv = 1.f / 1048576.f;
                float mu = a * inv;
                float var = b * inv - mu * mu;
                stats[sl2 * 2] = mu;
                stats[sl2 * 2 + 1] = rsqrtf(var + 1e-5f);
            }
        }
        __syncthreads();
        if (threadIdx.x == 0) { __threadfence(); g_flag = 1; }
    }
    // all 128 blocks co-resident (<=148 SMs) -> safe spin
    if (threadIdx.x == 0) { while (g_flag == 0) { } }
    __syncthreads();
    float mu = stats[slab * 2], rstd = stats[slab * 2 + 1];
    // normalize cached chunk: element idx = (base4 + tid + i*256)*4 ; c = idx & 255
    uint2* dst = reinterpret_cast<uint2*>(xn) + base4;
#pragma unroll
    for (int i = 0; i < 32; i++) {
        const int e4 = (int)((base4 + threadIdx.x + (i << 8)) & 63);  // float4 within 256-ch row
        const int c = e4 << 2;
        float4 v = cache[i];
        float n0 = (v.x - mu) * rstd * w[c]     + bb[c];
        float n1 = (v.y - mu) * rstd * w[c + 1] + bb[c + 1];
        float n2 = (v.z - mu) * rstd * w[c + 2] + bb[c + 2];
        float n3 = (v.w - mu) * rstd * w[c + 3] + bb[c + 3];
        __half2 h0 = __floats2half2_rn(n0, n1);
        __half2 h1 = __floats2half2_rn(n2, n3);
        uint2 pk;
        pk.x = *reinterpret_cast<uint32_t*>(&h0);
        pk.y = *reinterpret_cast<uint32_t*>(&h1);
        dst[threadIdx.x + (i << 8)] = pk;
    }
    __syncthreads();
    if (threadIdx.x == 0) {
        if (atomicInc(&g_cnt3, 0xFFFFFFFFu) == 127) {
            g_flag = 0; g_cnt2 = 0; g_cnt3 = 0;
            __threadfence();
        }
    }
}

// ---------------- normalize + NCHW->NHWC pack (half2 stores, 64-ch tiles) ----------------
__global__ void norm_pack_k(const float* __restrict__ xq, const float* __restrict__ xkv,
                            const float* __restrict__ stats, const float* __restrict__ w,
                            const float* __restrict__ bb, __half* __restrict__ xall) {
    __shared__ float tile[64][33];
    int bz = blockIdx.z;
    int tensor = bz >> 2, batch = bz & 3;
    const float* src = (tensor == 0 ? xq : xkv) + ((size_t)batch << 20);
    float mu = stats[bz * 2], rstd = stats[bz * 2 + 1];
    int s0 = blockIdx.x * 32, c0 = blockIdx.y * 64;
    int tx = threadIdx.x, ty = threadIdx.y;
#pragma unroll
    for (int k = 0; k < 8; k++) {
        int c = c0 + ty + k * 8;
        tile[ty + k * 8][tx] = src[(size_t)c * 4096 + s0 + tx];
    }
    __syncthreads();
    int c = c0 + 2 * tx;
    float w0 = w[c], w1 = w[c + 1], bb0 = bb[c], bb1 = bb[c + 1];
#pragma unroll
    for (int k = 0; k < 4; k++) {
        int sl = ty + k * 8;
        float v0 = (tile[2 * tx][sl] - mu) * rstd * w0 + bb0;
        float v1 = (tile[2 * tx + 1][sl] - mu) * rstd * w1 + bb1;
        __half2 hv = __floats2half2_rn(v0, v1);
        *reinterpret_cast<uint32_t*>(
            xall + (((size_t)batch * 4096 + s0 + sl) << 9) + tensor * 256 + c) =
            *reinterpret_cast<uint32_t*>(&hv);
    }
}

// ---------------- winograd input transform ----------------
__global__ void wino_in_k(const __half* __restrict__ xall, __half* __restrict__ U) {
    int id = blockIdx.x * 256 + threadIdx.x;
    int c2 = id & 255, t = id >> 8;
    int c = c2 << 1;
    int b = t >> 10, sp = t & 1023, ty = sp >> 5, tx = sp & 31;
    int y0 = (ty << 1) - 1, x0 = (tx << 1) - 1;
    float d0[4][4], d1[4][4];
#pragma unroll
    for (int i = 0; i < 4; i++) {
        int yy = y0 + i;
#pragma unroll
        for (int j = 0; j < 4; j++) {
            int xx = x0 + j;
            if (yy >= 0 && yy < 64 && xx >= 0 && xx < 64) {
                uint32_t v = *reinterpret_cast<const uint32_t*>(
                    xall + (((size_t)(b << 12) + (yy << 6) + xx) << 9) + c);
                float2 f = __half22float2(*reinterpret_cast<__half2*>(&v));
                d0[i][j] = f.x; d1[i][j] = f.y;
            } else { d0[i][j] = 0.f; d1[i][j] = 0.f; }
        }
    }
    float t0[4][4], t1[4][4];
#pragma unroll
    for (int j = 0; j < 4; j++) {
        t0[0][j] = d0[0][j] - d0[2][j]; t1[0][j] = d1[0][j] - d1[2][j];
        t0[1][j] = d0[1][j] + d0[2][j]; t1[1][j] = d1[1][j] + d1[2][j];
        t0[2][j] = d0[2][j] - d0[1][j]; t1[2][j] = d1[2][j] - d1[1][j];
        t0[3][j] = d0[1][j] - d0[3][j]; t1[3][j] = d1[1][j] - d1[3][j];
    }
#pragma unroll
    for (int i = 0; i < 4; i++) {
        float u0[4], u1[4];
        u0[0] = t0[i][0] - t0[i][2]; u1[0] = t1[i][0] - t1[i][2];
        u0[1] = t0[i][1] + t0[i][2]; u1[1] = t1[i][1] + t1[i][2];
        u0[2] = t0[i][2] - t0[i][1]; u1[2] = t1[i][2] - t1[i][1];
        u0[3] = t0[i][1] - t0[i][3]; u1[3] = t1[i][1] - t1[i][3];
#pragma unroll
        for (int j = 0; j < 4; j++) {
            __half2 hv = __floats2half2_rn(u0[j], u1[j]);
            *reinterpret_cast<uint32_t*>(
                U + (((size_t)(i * 4 + j) * 4096 + t) << 9) + c) =
                *reinterpret_cast<uint32_t*>(&hv);
        }
    }
}

// ---------------- winograd output transform (bias + relu) ----------------
__global__ void wino_out_k(const __half* __restrict__ V, const float* __restrict__ bias,
                           __half* __restrict__ h1) {
    int id = blockIdx.x * 256 + threadIdx.x;
    int o2 = id & 127, t = id >> 7;
    int o = o2 << 1;
    int b = t >> 10, sp = t & 1023, ty = sp >> 5, tx = sp & 31;
    float m0[4][4], m1[4][4];
#pragma unroll
    for (int i = 0; i < 4; i++)
#pragma unroll
        for (int j = 0; j < 4; j++) {
            uint32_t v = *reinterpret_cast<const uint32_t*>(
                V + (((size_t)(i * 4 + j) * 4096 + t) << 8) + o);
            float2 f = __half22float2(*reinterpret_cast<__half2*>(&v));
            m0[i][j] = f.x; m1[i][j] = f.y;
        }
    float b0 = bias[o], b1 = bias[o + 1];
    float p00[4], p01[4], p10[4], p11[4];
#pragma unroll
    for (int j = 0; j < 4; j++) {
        p00[j] = m0[0][j] + m0[1][j] + m0[2][j];
        p01[j] = m0[1][j] - m0[2][j] - m0[3][j];
        p10[j] = m1[0][j] + m1[1][j] + m1[2][j];
        p11[j] = m1[1][j] - m1[2][j] - m1[3][j];
    }
    float y0[2][2], y1[2][2];
    y0[0][0] = p00[0] + p00[1] + p00[2];  y0[0][1] = p00[1] - p00[2] - p00[3];
    y0[1][0] = p01[0] + p01[1] + p01[2];  y0[1][1] = p01[1] - p01[2] - p01[3];
    y1[0][0] = p10[0] + p10[1] + p10[2];  y1[0][1] = p10[1] - p10[2] - p10[3];
    y1[1][0] = p11[0] + p11[1] + p11[2];  y1[1][1] = p11[1] - p11[2] - p11[3];
#pragma unroll
    for (int r = 0; r < 2; r++)
#pragma unroll
        for (int cc = 0; cc < 2; cc++) {
            float v0 = fmaxf(y0[r][cc] + b0, 0.f);
            float v1 = fmaxf(y1[r][cc] + b1, 0.f);
            __half2 hv = __floats2half2_rn(v0, v1);
            int py = (ty << 1) + r, px = (tx << 1) + cc;
            *reinterpret_cast<uint32_t*>(
                h1 + (((size_t)(b << 12) + (py << 6) + px) << 8) + o) =
                *reinterpret_cast<uint32_t*>(&hv);
        }
}

// ---------------- PTX helpers ----------------
__device__ __forceinline__ void mma16(float4& d, const uint32_t* a, const uint32_t* b) {
    asm volatile("mma.sync.aligned.m16n8k16.row.col.f32.f16.f16.f32 "
        "{%0,%1,%2,%3}, {%4,%5,%6,%7}, {%8,%9}, {%0,%1,%2,%3};\n"
        : "+f"(d.x), "+f"(d.y), "+f"(d.z), "+f"(d.w)
        : "r"(a[0]), "r"(a[1]), "r"(a[2]), "r"(a[3]), "r"(b[0]), "r"(b[1]));
}
__device__ __forceinline__ void ldsm4(uint32_t* r, uint32_t a) {
    asm volatile("ldmatrix.sync.aligned.m8n8.x4.shared.b16 {%0,%1,%2,%3}, [%4];"
        : "=r"(r[0]), "=r"(r[1]), "=r"(r[2]), "=r"(r[3]) : "r"(a));
}
__device__ __forceinline__ void cp16(uint32_t d, const void* s, int sz) {
    asm volatile("cp.async.cg.shared.global [%0], [%1], 16, %2;"
        :: "r"(d), "l"(s), "r"(sz));
}
#define CP_COMMIT() asm volatile("cp.async.commit_group;")

// ---------------- multi-job fp16 tensor-core GEMM ----------------
#define STG_BYTES 32768
#define SMEM_REQ  (3 * STG_BYTES)

struct GJob {
    const __half* A; const __half* W; const float* bias; float* C; const float* R;
    int N, K, lda, mode, wino; float scale;
};

__device__ __forceinline__ void issue_tile(
    uint32_t sa0, const __half* __restrict__ A, const __half* __restrict__ W,
    int bm, int bn, int K0, int lda, int K, int lrow, int g)
{
    uint32_t sa = sa0 + lrow * 128;
    const __half* srcA = A + (size_t)(bm + lrow) * lda + K0;
    const __half* srcB = W + (size_t)(bn + lrow) * (size_t)K + K0;
    const int r7 = lrow & 7;
#pragma unroll
    for (int j = 0; j < 4; j++) {
        const int c = g + j;
        const uint32_t off = (uint32_t)((c ^ r7) << 4);
        cp16(sa + off, srcA + c * 8, 16);
        cp16(sa + 16384 + off, srcB + c * 8, 16);
    }
}

__global__ void __launch_bounds__(256, 2) gemm_tc(
    GJob j0, GJob j1, GJob j2, int c0, int c1)
{
    extern __shared__ float smbuf[];
    const uint32_t smem_base = (uint32_t)__cvta_generic_to_shared(smbuf);

    GJob J;
    int local;
    {
        const int id = blockIdx.x;
        if (id < c0)      { J = j0; local = id; }
        else if (id < c1) { J = j1; local = id - c0; }
        else              { J = j2; local = id - c1; }
    }
    const int bnb = J.N >> 7;
    const int bm = (local / bnb) << 7, bn = (local % bnb) << 7;
    if (J.wino) J.W += ((size_t)(bm >> 12)) << 17;

    const int tid  = threadIdx.x;
    const int warp = tid >> 5, lane = tid & 31;
    const int wm   = (warp >> 2) << 6, wn = (warp & 3) << 5;
    const int lg   = lane >> 2, la3 = lane & 3;

    const int lrow = tid >> 1, g = (tid & 1) * 4;

    const int l7 = lane & 7, lq = lane >> 3;
    uint32_t arow[4], brow[2];
#pragma unroll
    for (int mt = 0; mt < 4; mt++)
        arow[mt] = (uint32_t)((wm + mt * 16 + ((lq & 1) << 3) + l7) * 128);
    const int a_kq = lq >> 1;
#pragma unroll
    for (int p = 0; p < 2; p++)
        brow[p] = (uint32_t)(16384 + (wn + p * 16 + ((lq >> 1) << 3) + l7) * 128);
    const int b_kq = lq & 1;

    float4 acc[4][4];
#pragma unroll
    for (int i = 0; i < 4; i++)
#pragma unroll
        for (int j = 0; j < 4; j++) acc[i][j] = make_float4(0.f, 0.f, 0.f, 0.f);

    const int nkb = J.K >> 6;
    issue_tile(smem_base,             J.A, J.W, bm, bn,  0, J.lda, J.K, lrow, g);
    CP_COMMIT();
    issue_tile(smem_base + STG_BYTES, J.A, J.W, bm, bn, 64, J.lda, J.K, lrow, g);
    CP_COMMIT();

    int stg = 0;
    for (int kb = 0; kb < nkb; kb++) {
        asm volatile("cp.async.wait_group 1;");
        __syncthreads();
        if (kb + 2 < nkb) {
            int s2 = stg + 2; if (s2 >= 3) s2 -= 3;
            issue_tile(smem_base + s2 * STG_BYTES, J.A, J.W, bm, bn,
                       (kb + 2) << 6, J.lda, J.K, lrow, g);
        }
        CP_COMMIT();

        const uint32_t Ab = smem_base + stg * STG_BYTES;
#pragma unroll
        for (int ks = 0; ks < 4; ks++) {
            const uint32_t axor = (uint32_t)((((ks << 1) + a_kq) ^ l7) << 4);
            const uint32_t bxor = (uint32_t)((((ks << 1) + b_kq) ^ l7) << 4);
            uint32_t af[4][4], bf[2][4];
#pragma unroll
            for (int mt = 0; mt < 4; mt++) ldsm4(af[mt], Ab + arow[mt] + axor);
#pragma unroll
            for (int p = 0; p < 2; p++)    ldsm4(bf[p],  Ab + brow[p] + bxor);
#pragma unroll
            for (int mt = 0; mt < 4; mt++) {
                mma16(acc[mt][0], af[mt], &bf[0][0]);
                mma16(acc[mt][1], af[mt], &bf[0][2]);
                mma16(acc[mt][2], af[mt], &bf[1][0]);
                mma16(acc[mt][3], af[mt], &bf[1][2]);
            }
        }
        if (++stg == 3) stg = 0;
    }

    // ---------------- epilogue ----------------
    const bool halfout = (J.mode == 1) || (J.mode == 2) || (J.mode == 3) || (J.mode == 6);
#pragma unroll
    for (int mt = 0; mt < 4; mt++) {
        const int m0 = bm + wm + (mt << 4) + lg;
#pragma unroll
        for (int nt = 0; nt < 4; nt++) {
            const int n = bn + wn + (nt << 3) + (la3 << 1);
            const float b0 = J.bias[n], b1 = J.bias[n + 1];
            float v[4] = {acc[mt][nt].x + b0, acc[mt][nt].y + b1,
                          acc[mt][nt].z + b0, acc[mt][nt].w + b1};
#pragma unroll
            for (int h = 0; h < 2; h++) {
                const int m = m0 + h * 8;
                if (halfout) {
                    float x0 = v[h * 2], x1 = v[h * 2 + 1];
                    if (J.mode == 1) { x0 *= J.scale; x1 *= J.scale; }
                    else if (J.mode == 2) { x0 = fmaxf(x0, 0.f); x1 = fmaxf(x1, 0.f); }
                    else if (J.mode == 3) {
                        x0 = 0.5f * x0 * (1.f + erff(x0 * 0.70710678118654752f));
                        x1 = 0.5f * x1 * (1.f + erff(x1 * 0.70710678118654752f));
                    }
                    *reinterpret_cast<__half2*>(
                        reinterpret_cast<__half*>(J.C) + (size_t)m * (size_t)J.N + n) =
                        __floats2half2_rn(x0, x1);
                } else {
#pragma unroll
                    for (int j = 0; j < 2; j++) {
                        float x = v[h * 2 + j];
                        const int nn = n + j;
                        if (J.mode == 4) x += J.R[((size_t)(m >> 12) * 256 + nn) * 4096 + (m & 4095)];
                        else if (J.mode == 5) x += J.R[(size_t)m * 256 + nn];
                        if (J.mode == 5)
                            J.C[((size_t)(m >> 12) * 256 + nn) * 4096 + (m & 4095)] = x;
                        else
                            J.C[(size_t)m * (size_t)J.N + nn] = x;
                    }
                }
            }
        }
    }
}

// ---------------- offset head (fp16 h1) ----------------
__global__ void off2_k(const __half* __restrict__ h1, const float* __restrict__ w,
                       const float* __restrict__ bias, float* __restrict__ offs) {
    int id = blockIdx.x * blockDim.x + threadIdx.x;
    if (id >= MTOT * 18) return;
    int m = id / 18, n = id - m * 18;
    const uint4* a = reinterpret_cast<const uint4*>(h1 + (size_t)m * 256);
    const float4* ww = reinterpret_cast<const float4*>(w + (size_t)n * 256);
    float s = bias[n];
#pragma unroll 8
    for (int k = 0; k < 32; k++) {
        uint4 av = a[k];
        const __half2* hh = reinterpret_cast<const __half2*>(&av);
        float2 f0 = __half22float2(hh[0]), f1 = __half22float2(hh[1]);
        float2 f2 = __half22float2(hh[2]), f3 = __half22float2(hh[3]);
        float4 w0 = ww[2 * k], w1 = ww[2 * k + 1];
        s += f0.x * w0.x + f0.y * w0.y + f1.x * w0.z + f1.y * w0.w;
        s += f2.x * w1.x + f2.y * w1.y + f3.x * w1.z + f3.y * w1.w;
    }
    offs[id] = s;
}

// ---------------- fused bilinear-sample + 9-way attention (fp16) ----------------
#define LOAD8H(dst, ptr)                                                    \
    {                                                                       \
        uint4 _u = *reinterpret_cast<const uint4*>(ptr);                    \
        __half2* _hh = reinterpret_cast<__half2*>(&_u);                     \
        float2 _f0 = __half22float2(_hh[0]), _f1 = __half22float2(_hh[1]);  \
        float2 _f2 = __half22float2(_hh[2]), _f3 = __half22float2(_hh[3]);  \
        dst[0] = _f0.x; dst[1] = _f0.y; dst[2] = _f1.x; dst[3] = _f1.y;     \
        dst[4] = _f2.x; dst[5] = _f2.y; dst[6] = _f3.x; dst[7] = _f3.y;     \
    }

__global__ void __launch_bounds__(256) attn_k(
    const __half* __restrict__ qb, const __half* __restrict__ kv,
    const float* __restrict__ offs, __half* __restrict__ outp) {
    __shared__ float sh[8][9][8];
    const int warp = threadIdx.x >> 5, lane = threadIdx.x & 31;
    const int p = blockIdx.x * 8 + warp;
    const int b = p >> 12, s = p & 4095, y = s >> 6, x = s & 63;
    const __half* kvb = kv + (((size_t)b << 12) << 9);

    float qr[8];
    LOAD8H(qr, qb + (size_t)p * 256 + lane * 8);

    for (int o = 0; o < 9; o++) {
        int ys = y + o / 3 - 1, xs = x + o % 3 - 1;
        float prod[8] = {0.f, 0.f, 0.f, 0.f, 0.f, 0.f, 0.f, 0.f};
        if (ys >= 0 && ys < 64 && xs >= 0 && xs < 64) {
            const float* op = offs + (size_t)((b << 12) + (ys << 6) + xs) * 18 + 2 * o;
            float px = op[0], py = op[1];
            float y0f = floorf(py), x0f = floorf(px);
            float wy = py - y0f, wx = px - x0f;
            int y0 = (int)y0f, x0 = (int)x0f;
            float w00 = (1.f - wy) * (1.f - wx), w01 = (1.f - wy) * wx;
            float w10 = wy * (1.f - wx), w11 = wy * wx;
            bool vy0 = (y0 >= 0) && (y0 < 64), vy1 = (y0 + 1 >= 0) && (y0 + 1 < 64);
            bool vx0 = (x0 >= 0) && (x0 < 64), vx1 = (x0 + 1 >= 0) && (x0 + 1 < 64);
            w00 = (vy0 && vx0) ? w00 : 0.f; w01 = (vy0 && vx1) ? w01 : 0.f;
            w10 = (vy1 && vx0) ? w10 : 0.f; w11 = (vy1 && vx1) ? w11 : 0.f;
            int y0c = min(max(y0, 0), 63), y1c = min(max(y0 + 1, 0), 63);
            int x0c = min(max(x0, 0), 63), x1c = min(max(x0 + 1, 0), 63);
            float c00[8], c01[8], c10[8], c11[8];
            LOAD8H(c00, kvb + ((size_t)((y0c << 6) + x0c) << 9) + lane * 8);
            LOAD8H(c01, kvb + ((size_t)((y0c << 6) + x1c) << 9) + lane * 8);
            LOAD8H(c10, kvb + ((size_t)((y1c << 6) + x0c) << 9) + lane * 8);
            LOAD8H(c11, kvb + ((size_t)((y1c << 6) + x1c) << 9) + lane * 8);
#pragma unroll
            for (int h = 0; h < 8; h++) {
                float kvv = w00 * c00[h] + w01 * c01[h] + w10 * c10[h] + w11 * c11[h];
                prod[h] = qr[h] * kvv;
            }
        }
#pragma unroll
        for (int off = 16; off > 0; off >>= 1)
#pragma unroll
            for (int h = 0; h < 8; h++)
                prod[h] += __shfl_xor_sync(0xffffffffu, prod[h], off);
        if (lane == 0) {
#pragma unroll
            for (int h = 0; h < 8; h++) sh[warp][o][h] = prod[h];
        }
    }
    __syncwarp();
    if (lane < 8) {
        float e[9]; float mx = -1e30f;
#pragma unroll
        for (int o = 0; o < 9; o++) { e[o] = sh[warp][o][lane]; mx = fmaxf(mx, e[o]); }
        float sm = 0.f;
#pragma unroll
        for (int o = 0; o < 9; o++) { e[o] = expf(e[o] - mx); sm += e[o]; }
        float inv = 1.f / sm;
#pragma unroll
        for (int o = 0; o < 9; o++) sh[warp][o][lane] = e[o] * inv;
    }
    __syncwarp();
    float acc[8] = {0.f, 0.f, 0.f, 0.f, 0.f, 0.f, 0.f, 0.f};
    for (int o = 0; o < 9; o++) {
        int ys = y + o / 3 - 1, xs = x + o % 3 - 1;
        if (ys < 0 || ys >= 64 || xs < 0 || xs >= 64) continue;
        const float* op = offs + (size_t)((b << 12) + (ys << 6) + xs) * 18 + 2 * o;
        float px = op[0], py = op[1];
        float y0f = floorf(py), x0f = floorf(px);
        float wy = py - y0f, wx = px - x0f;
        int y0 = (int)y0f, x0 = (int)x0f;
        float w00 = (1.f - wy) * (1.f - wx), w01 = (1.f - wy) * wx;
        float w10 = wy * (1.f - wx), w11 = wy * wx;
        bool vy0 = (y0 >= 0) && (y0 < 64), vy1 = (y0 + 1 >= 0) && (y0 + 1 < 64);
        bool vx0 = (x0 >= 0) && (x0 < 64), vx1 = (x0 + 1 >= 0) && (x0 + 1 < 64);
        w00 = (vy0 && vx0) ? w00 : 0.f; w01 = (vy0 && vx1) ? w01 : 0.f;
        w10 = (vy1 && vx0) ? w10 : 0.f; w11 = (vy1 && vx1) ? w11 : 0.f;
        int y0c = min(max(y0, 0), 63), y1c = min(max(y0 + 1, 0), 63);
        int x0c = min(max(x0, 0), 63), x1c = min(max(x0 + 1, 0), 63);
        float c00[8], c01[8], c10[8], c11[8];
        LOAD8H(c00, kvb + ((size_t)((y0c << 6) + x0c) << 9) + 256 + lane * 8);
        LOAD8H(c01, kvb + ((size_t)((y0c << 6) + x1c) << 9) + 256 + lane * 8);
        LOAD8H(c10, kvb + ((size_t)((y1c << 6) + x0c) << 9) + 256 + lane * 8);
        LOAD8H(c11, kvb + ((size_t)((y1c << 6) + x1c) << 9) + 256 + lane * 8);
#pragma unroll
        for (int h = 0; h < 8; h++) {
            float vv = w00 * c00[h] + w01 * c01[h] + w10 * c10[h] + w11 * c11[h];
            acc[h] += sh[warp][o][h] * vv;
        }
    }
    __half2 h0 = __floats2half2_rn(acc[0], acc[1]);
    __half2 h1 = __floats2half2_rn(acc[2], acc[3]);
    __half2 h2 = __floats2half2_rn(acc[4], acc[5]);
    __half2 h3 = __floats2half2_rn(acc[6], acc[7]);
    uint4 pk;
    pk.x = *reinterpret_cast<uint32_t*>(&h0);
    pk.y = *reinterpret_cast<uint32_t*>(&h1);
    pk.z = *reinterpret_cast<uint32_t*>(&h2);
    pk.w = *reinterpret_cast<uint32_t*>(&h3);
    *reinterpret_cast<uint4*>(outp + (size_t)p * 256 + lane * 8) = pk;
}

// ---------------- host ----------------
extern "C" void kernel_launch(void* const* d_in, const int* in_sizes, int n_in,
                              void* d_out, int out_size) {
    const float* x_q    = (const float*)d_in[0];
    const float* x_kv   = (const float*)d_in[1];
    const float* n1w    = (const float*)d_in[2];
    const float* n1b    = (const float*)d_in[3];
    const float* q_w    = (const float*)d_in[4];
    const float* q_b    = (const float*)d_in[5];
    const float* kv_w   = (const float*)d_in[6];
    const float* kv_b   = (const float*)d_in[7];
    const float* off1_w = (const float*)d_in[8];
    const float* off1_b = (const float*)d_in[9];
    const float* off2_w = (const float*)d_in[10];
    const float* off2_b = (const float*)d_in[11];
    const float* proj_w = (const float*)d_in[12];
    const float* proj_b = (const float*)d_in[13];
    const float* n2w    = (const float*)d_in[14];
    const float* n2b    = (const float*)d_in[15];
    const float* fc1_w  = (const float*)d_in[16];
    const float* fc1_b  = (const float*)d_in[17];
    const float* fc2_w  = (const float*)d_in[18];
    const float* fc2_b  = (const float*)d_in[19];
    float* out = (float*)d_out;

    __half *xall, *qb, *kvb, *h1, *att, *xn2, *hid, *wrw, *wh, *U, *V;
    float *offs, *xres, *st1, *st2, *zerob;
    float2* part;
    cudaGetSymbolAddress((void**)&xall, g_xall);
    cudaGetSymbolAddress((void**)&qb,   g_q);
    cudaGetSymbolAddress((void**)&kvb,  g_kv);
    cudaGetSymbolAddress((void**)&h1,   g_h1);
    cudaGetSymbolAddress((void**)&U,    g_U);
    cudaGetSymbolAddress((void**)&V,    g_V);
    cudaGetSymbolAddress((void**)&offs, g_offs);
    cudaGetSymbolAddress((void**)&att,  g_att);
    cudaGetSymbolAddress((void**)&xres, g_xres);
    cudaGetSymbolAddress((void**)&xn2,  g_xn2);
    cudaGetSymbolAddress((void**)&hid,  g_hid);
    cudaGetSymbolAddress((void**)&wrw,  g_wrw);
    cudaGetSymbolAddress((void**)&wh,   g_wh);
    cudaGetSymbolAddress((void**)&zerob,g_zero);
    cudaGetSymbolAddress((void**)&part, g_part);
    cudaGetSymbolAddress((void**)&st1,  g_st1);
    cudaGetSymbolAddress((void**)&st2,  g_st2);

    __half* qwh  = wh;
    __half* kvwh = qwh  + 65536;
    __half* pwh  = kvwh + 131072;
    __half* f1wh = pwh  + 65536;
    __half* f2wh = f1wh + 262144;

    cudaFuncSetAttribute(gemm_tc, cudaFuncAttributeMaxDynamicSharedMemorySize, SMEM_REQ);

    front_k<<<3840, 256>>>(off1_w, wrw, q_w, qwh, kv_w, kvwh, proj_w, pwh,
                           fc1_w, f1wh, fc2_w, f2wh, x_q, x_kv, part, st1);
    norm_pack_k<<<dim3(128, 4, 8), dim3(32, 8)>>>(x_q, x_kv, st1, n1w, n1b, xall);
    wino_in_k<<<4096, 256>>>(xall, U);

    GJob zero = {};
    // fused winograd-conv + kv + q
    {
        GJob jw  = {U,           wrw,  zerob, (float*)V,   nullptr, 256, 512, 512, 6, 1, 0.f};
        GJob jkv = {xall + 256,  kvwh, kv_b,  (float*)kvb, nullptr, 512, 256, 512, 6, 0, 0.f};
        GJob jq  = {xall,        qwh,  q_b,   (float*)qb,  nullptr, 256, 256, 512, 1, 0,
                    0.17677669529663689f};
        gemm_tc<<<1792, 256, SMEM_REQ>>>(jw, jkv, jq, 1024, 1536);
    }
    wino_out_k<<<2048, 256>>>(V, off1_b, h1);
    off2_k<<<(MTOT * 18) / 256, 256>>>(h1, off2_w, off2_b, offs);
    attn_k<<<2048, 256>>>(qb, kvb, offs, att);
    // xres = x_q + att @ proj_w^T + b
    {
        GJob jp = {att, pwh, proj_b, xres, x_q, 256, 256, 256, 4, 0, 0.f};
        gemm_tc<<<256, 256, SMEM_REQ>>>(jp, zero, zero, 256, 256);
    }
    // fused xres stats + norm2 (spin on co-resident 128 blocks)
    gnxn_k<<<128, 256>>>(xres, part, st2, n2w, n2b, xn2);
    // hid = gelu(xn2 @ fc1_w^T + b) -> half
    {
        GJob jf1 = {xn2, f1wh, fc1_b, (float*)hid, nullptr, 1024, 256, 256, 3, 0, 0.f};
        gemm_tc<<<1024, 256, SMEM_REQ>>>(jf1, zero, zero, 1024, 1024);
    }
    // out(NCHW) = xres + hid @ fc2_w^T + b   (256 CTAs)
    {
        GJob jf2 = {hid, f2wh, fc2_b, out, xres, 256, 1024, 1024, 5, 0, 0.f};
        gemm_tc<<<256, 256, SMEM_REQ>>>(jf2, zero, zero, 256, 256);
    }
}